// round 7
// baseline (speedup 1.0000x reference)
#include <cuda_runtime.h>
#include <cuda_bf16.h>

typedef unsigned int u32;

// ---------------- problem constants ----------------
#define NS    65536
#define KEXP  8
#define DIN   74
#define WID   64
#define DOUT  32
#define TILE  256
#define NT    512
#define MAXTILES (NS / TILE + KEXP)
#define NSCAT 256

// ---------------- smem layout (bytes) ----------------
#define SM_XH0  0                  // A/H hi panel0: [256 rows][128B] (k 0..63)
#define SM_XL0  32768
#define SM_XH1  65536              // A hi panel1: [256 rows][48B] (k 64..79)
#define SM_XL1  77824
#define SM_W0H0 90112              // W0^T hi p0: [64 n][128B]
#define SM_W0H1 98304              // W0^T hi p1: [64 n][48B]
#define SM_W0L0 101376
#define SM_W0L1 109568
#define SM_W1H  112640             // W1^T hi: [64 n][128B]
#define SM_W1L  120832
#define SM_W2H  129024             // W2^T hi: [32 n][128B]
#define SM_W2L  133120
#define SM_GH   137216             // layer-2 input: [256][128B]
#define SM_GL   169984
#define SM_B0   202752
#define SM_B1   203008
#define SM_B2   203264
#define SM_SIDS 203392
#define SMEM_BYTES (SM_SIDS + TILE * 4)   // 204416

#define SWZ(off) ((off) ^ (((off) >> 3) & 0x70))

// ---------------- device scratch ----------------
__device__ int g_hist[KEXP];
__device__ int g_offs[KEXP + 1];
__device__ int g_cursor[KEXP];
__device__ int g_order[NS];

// ---------------- bucketing ----------------
__global__ void k_hist(const int* __restrict__ idxs) {
    __shared__ int sh[KEXP];
    if (threadIdx.x < KEXP) sh[threadIdx.x] = 0;
    __syncthreads();
    atomicAdd(&sh[idxs[blockIdx.x * 256 + threadIdx.x]], 1);
    __syncthreads();
    if (threadIdx.x < KEXP) atomicAdd(&g_hist[threadIdx.x], sh[threadIdx.x]);
}
__global__ void k_scan() {
    int acc = 0;
    for (int e = 0; e < KEXP; e++) {
        g_offs[e] = acc; g_cursor[e] = acc;
        acc += g_hist[e];
        g_hist[e] = 0;
    }
    g_offs[KEXP] = acc;
}
__global__ void k_scatter(const int* __restrict__ idxs) {
    __shared__ int s_loc[KEXP];
    __shared__ int s_base[KEXP];
    if (threadIdx.x < KEXP) s_loc[threadIdx.x] = 0;
    __syncthreads();
    int i = blockIdx.x * 256 + threadIdx.x;
    int e = idxs[i];
    int r = atomicAdd(&s_loc[e], 1);
    __syncthreads();
    if (threadIdx.x < KEXP)
        s_base[threadIdx.x] = atomicAdd(&g_cursor[threadIdx.x], s_loc[threadIdx.x]);
    __syncthreads();
    g_order[s_base[e] + r] = i;
}

// ---------------- PTX helpers (baseline ISA only) ----------------
__device__ __forceinline__ u32 smem_u32(const void* p) {
    u32 a; asm("{ .reg .u64 t; cvta.to.shared.u64 t, %1; cvt.u32.u64 %0, t; }" : "=r"(a) : "l"(p));
    return a;
}
__device__ __forceinline__ void ldmA(u32 a[4], u32 addr) {
    asm volatile("ldmatrix.sync.aligned.m8n8.x4.shared.b16 {%0,%1,%2,%3}, [%4];"
                 : "=r"(a[0]), "=r"(a[1]), "=r"(a[2]), "=r"(a[3]) : "r"(addr));
}
__device__ __forceinline__ void ldmB(u32 b[2], u32 addr) {
    asm volatile("ldmatrix.sync.aligned.m8n8.x2.shared.b16 {%0,%1}, [%2];"
                 : "=r"(b[0]), "=r"(b[1]) : "r"(addr));
}
__device__ __forceinline__ void mma16816(float c[4], const u32 a[4], const u32 b[2]) {
    asm volatile(
        "mma.sync.aligned.m16n8k16.row.col.f32.bf16.bf16.f32 "
        "{%0,%1,%2,%3}, {%4,%5,%6,%7}, {%8,%9}, {%0,%1,%2,%3};"
        : "+f"(c[0]), "+f"(c[1]), "+f"(c[2]), "+f"(c[3])
        : "r"(a[0]), "r"(a[1]), "r"(a[2]), "r"(a[3]), "r"(b[0]), "r"(b[1]));
}
__device__ __forceinline__ u32 bpack(__nv_bfloat16 a, __nv_bfloat16 b) {
    __nv_bfloat162 t(a, b);
    return *reinterpret_cast<u32*>(&t);
}
__device__ __forceinline__ void store_split(char* sm, u32 offH, u32 offL, float v0, float v1) {
    __nv_bfloat16 h0 = __float2bfloat16(v0), h1 = __float2bfloat16(v1);
    float l0 = v0 - __bfloat162float(h0), l1 = v1 - __bfloat162float(h1);
    *(u32*)(sm + offH) = bpack(h0, h1);
    *(u32*)(sm + offL) = bpack(__float2bfloat16(l0), __float2bfloat16(l1));
}

// ---------------- fused MMA MLP kernel ----------------
__global__ void __launch_bounds__(NT, 1) k_mlp(
    const float* __restrict__ positions, const float* __restrict__ viewdirs,
    const float* __restrict__ features,
    const float* __restrict__ W0g, const float* __restrict__ b0g,
    const float* __restrict__ W1g, const float* __restrict__ b1g,
    const float* __restrict__ W2g, const float* __restrict__ b2g,
    float* __restrict__ out) {
    extern __shared__ char sm[];
    const u32 smb = smem_u32(sm);
    const int tid = threadIdx.x, lane = tid & 31, wid = tid >> 5;

    // blockIdx -> (expert, local tile)
    int e = -1, lt = 0;
    {
        int b = blockIdx.x, acc = 0;
#pragma unroll
        for (int i = 0; i < KEXP; i++) {
            int tiles = (g_offs[i + 1] - g_offs[i] + TILE - 1) / TILE;
            if (e < 0 && b < acc + tiles) { e = i; lt = b - acc; }
            acc += tiles;
        }
    }
    if (e < 0) return;
    const int base = g_offs[e] + lt * TILE;
    const int cnt = min(TILE, g_offs[e + 1] - base);

    int* sids = (int*)(sm + SM_SIDS);
    float* B0s = (float*)(sm + SM_B0);
    float* B1s = (float*)(sm + SM_B1);
    float* B2s = (float*)(sm + SM_B2);

    // ================= STAGING =================
    if (tid < TILE) {
        int n = g_order[base + min(tid, cnt - 1)];   // pad partial tiles with a valid row
        sids[tid] = n;
        float x[80];
        const float4* f4 = (const float4*)(features + (size_t)n * 32);
#pragma unroll
        for (int i = 0; i < 8; i++) {
            float4 f = f4[i];
            x[4 * i] = f.x; x[4 * i + 1] = f.y; x[4 * i + 2] = f.z; x[4 * i + 3] = f.w;
        }
        float p0 = positions[n * 3], p1 = positions[n * 3 + 1], p2 = positions[n * 3 + 2];
        x[32] = p0; x[33] = p1; x[34] = p2;
#pragma unroll
        for (int s = 0; s < 2; s++) {
            float sc = (float)(1 << s);
            x[35 + 3 * s] = __sinf(p0 * sc); x[36 + 3 * s] = __sinf(p1 * sc); x[37 + 3 * s] = __sinf(p2 * sc);
            x[41 + 3 * s] = __cosf(p0 * sc); x[42 + 3 * s] = __cosf(p1 * sc); x[43 + 3 * s] = __cosf(p2 * sc);
        }
        float q0 = viewdirs[n * 3], q1 = viewdirs[n * 3 + 1], q2 = viewdirs[n * 3 + 2];
        x[47] = q0; x[48] = q1; x[49] = q2;
#pragma unroll
        for (int s = 0; s < 4; s++) {
            float sc = (float)(1 << s);
            x[50 + 3 * s] = __sinf(q0 * sc); x[51 + 3 * s] = __sinf(q1 * sc); x[52 + 3 * s] = __sinf(q2 * sc);
            x[62 + 3 * s] = __cosf(q0 * sc); x[63 + 3 * s] = __cosf(q1 * sc); x[64 + 3 * s] = __cosf(q2 * sc);
        }
#pragma unroll
        for (int k = DIN; k < 80; k++) x[k] = 0.0f;
#pragma unroll
        for (int j = 0; j < 40; j++) {
            if (j < 32) {
                u32 off = SWZ((u32)(tid * 128 + j * 4));
                store_split(sm, SM_XH0 + off, SM_XL0 + off, x[2 * j], x[2 * j + 1]);
            } else {
                u32 off = (u32)(tid * 48 + (j - 32) * 4);
                store_split(sm, SM_XH1 + off, SM_XL1 + off, x[2 * j], x[2 * j + 1]);
            }
        }
    } else {
        int t2 = tid - TILE;   // 0..255
        const float* W0e = W0g + e * DIN * WID;
        for (int i = t2; i < 80 * 64; i += 256) {
            int k = i >> 6, c = i & 63;
            float v = (k < DIN) ? W0e[k * WID + c] : 0.0f;
            __nv_bfloat16 h = __float2bfloat16(v);
            __nv_bfloat16 l = __float2bfloat16(v - __bfloat162float(h));
            if (k < 64) {
                u32 off = SWZ((u32)(c * 128 + k * 2));
                *(__nv_bfloat16*)(sm + SM_W0H0 + off) = h;
                *(__nv_bfloat16*)(sm + SM_W0L0 + off) = l;
            } else {
                u32 off = (u32)(c * 48 + (k - 64) * 2);
                *(__nv_bfloat16*)(sm + SM_W0H1 + off) = h;
                *(__nv_bfloat16*)(sm + SM_W0L1 + off) = l;
            }
        }
        const float* W1e = W1g + e * WID * WID;
        for (int i = t2; i < 64 * 64; i += 256) {
            int k = i >> 6, c = i & 63;
            float v = W1e[k * WID + c];
            __nv_bfloat16 h = __float2bfloat16(v);
            __nv_bfloat16 l = __float2bfloat16(v - __bfloat162float(h));
            u32 off = SWZ((u32)(c * 128 + k * 2));
            *(__nv_bfloat16*)(sm + SM_W1H + off) = h;
            *(__nv_bfloat16*)(sm + SM_W1L + off) = l;
        }
        const float* W2e = W2g + e * WID * DOUT;
        for (int i = t2; i < 64 * 32; i += 256) {
            int k = i >> 5, c = i & 31;
            float v = W2e[k * DOUT + c];
            __nv_bfloat16 h = __float2bfloat16(v);
            __nv_bfloat16 l = __float2bfloat16(v - __bfloat162float(h));
            u32 off = SWZ((u32)(c * 128 + k * 2));
            *(__nv_bfloat16*)(sm + SM_W2H + off) = h;
            *(__nv_bfloat16*)(sm + SM_W2L + off) = l;
        }
        if (t2 < WID) { B0s[t2] = b0g[e * WID + t2]; B1s[t2] = b1g[e * WID + t2]; }
        if (t2 >= WID && t2 < WID + DOUT) B2s[t2 - WID] = b2g[e * DOUT + t2 - WID];
    }
    __syncthreads();

    // fragment lane coordinates (warp grid: 8 M-groups x 2 N-groups)
    const int wm = wid >> 1, wn = wid & 1;
    const int amat = lane >> 3, amr = lane & 7;
    const int arow_off = ((amat & 1) << 3) + amr;
    const int akoff = amat >> 1;
    const int bmr = lane & 7, bmat = (lane >> 3) & 1;

    float C[2][4][4];

    // ================= LAYER 0 (K=80, N=64) =================
#pragma unroll
    for (int mt = 0; mt < 2; mt++)
#pragma unroll
        for (int nt = 0; nt < 4; nt++)
#pragma unroll
            for (int q = 0; q < 4; q++) C[mt][nt][q] = 0.0f;

#pragma unroll
    for (int mt = 0; mt < 2; mt++) {
        int arow = wm * 32 + mt * 16 + arow_off;
        u32 arb = (u32)(arow * 128);
        int ar7 = arow & 7;
        u32 ah[5][4], al[5][4];
#pragma unroll
        for (int kt = 0; kt < 4; kt++) {
            u32 off = arb + (u32)(((2 * kt + akoff) ^ ar7) << 4);
            ldmA(ah[kt], smb + SM_XH0 + off);
            ldmA(al[kt], smb + SM_XL0 + off);
        }
        {
            u32 off = (u32)(arow * 48 + (akoff << 4));
            ldmA(ah[4], smb + SM_XH1 + off);
            ldmA(al[4], smb + SM_XL1 + off);
        }
#pragma unroll
        for (int nt = 0; nt < 4; nt++) {
            int bn = wn * 32 + nt * 8 + bmr;
            u32 bnb = (u32)(bn * 128);
            int bn7 = bn & 7;
            u32 bh[5][2], bl[5][2];
#pragma unroll
            for (int kt = 0; kt < 4; kt++) {
                u32 off = bnb + (u32)(((2 * kt + bmat) ^ bn7) << 4);
                ldmB(bh[kt], smb + SM_W0H0 + off);
                ldmB(bl[kt], smb + SM_W0L0 + off);
            }
            {
                u32 off = (u32)(bn * 48 + (bmat << 4));
                ldmB(bh[4], smb + SM_W0H1 + off);
                ldmB(bl[4], smb + SM_W0L1 + off);
            }
#pragma unroll
            for (int kt = 0; kt < 5; kt++) {
                mma16816(C[mt][nt], ah[kt], bh[kt]);
                mma16816(C[mt][nt], ah[kt], bl[kt]);
                mma16816(C[mt][nt], al[kt], bh[kt]);
            }
        }
    }
    __syncthreads();   // all warps done reading X before H overwrites panel0

    // epilogue L0: bias+relu, split, write H into XH0/XL0
#pragma unroll
    for (int mt = 0; mt < 2; mt++)
#pragma unroll
        for (int nt = 0; nt < 4; nt++) {
            int row0 = wm * 32 + mt * 16 + (lane >> 2);
            int j0 = wn * 32 + nt * 8 + (lane & 3) * 2;
            float v0 = fmaxf(C[mt][nt][0] + B0s[j0], 0.0f);
            float v1 = fmaxf(C[mt][nt][1] + B0s[j0 + 1], 0.0f);
            float v2 = fmaxf(C[mt][nt][2] + B0s[j0], 0.0f);
            float v3 = fmaxf(C[mt][nt][3] + B0s[j0 + 1], 0.0f);
            u32 oa = SWZ((u32)(row0 * 128 + j0 * 2));
            u32 ob = SWZ((u32)((row0 + 8) * 128 + j0 * 2));
            store_split(sm, SM_XH0 + oa, SM_XL0 + oa, v0, v1);
            store_split(sm, SM_XH0 + ob, SM_XL0 + ob, v2, v3);
        }
    __syncthreads();

    // ================= LAYER 1 (K=64, N=64) =================
#pragma unroll
    for (int mt = 0; mt < 2; mt++)
#pragma unroll
        for (int nt = 0; nt < 4; nt++)
#pragma unroll
            for (int q = 0; q < 4; q++) C[mt][nt][q] = 0.0f;

#pragma unroll
    for (int mt = 0; mt < 2; mt++) {
        int arow = wm * 32 + mt * 16 + arow_off;
        u32 arb = (u32)(arow * 128);
        int ar7 = arow & 7;
        u32 ah[4][4], al[4][4];
#pragma unroll
        for (int kt = 0; kt < 4; kt++) {
            u32 off = arb + (u32)(((2 * kt + akoff) ^ ar7) << 4);
            ldmA(ah[kt], smb + SM_XH0 + off);
            ldmA(al[kt], smb + SM_XL0 + off);
        }
#pragma unroll
        for (int nt = 0; nt < 4; nt++) {
            int bn = wn * 32 + nt * 8 + bmr;
            u32 bnb = (u32)(bn * 128);
            int bn7 = bn & 7;
            u32 bh[4][2], bl[4][2];
#pragma unroll
            for (int kt = 0; kt < 4; kt++) {
                u32 off = bnb + (u32)(((2 * kt + bmat) ^ bn7) << 4);
                ldmB(bh[kt], smb + SM_W1H + off);
                ldmB(bl[kt], smb + SM_W1L + off);
            }
#pragma unroll
            for (int kt = 0; kt < 4; kt++) {
                mma16816(C[mt][nt], ah[kt], bh[kt]);
                mma16816(C[mt][nt], ah[kt], bl[kt]);
                mma16816(C[mt][nt], al[kt], bh[kt]);
            }
        }
    }
    __syncthreads();

    // epilogue L1: bias+relu, split, write G
#pragma unroll
    for (int mt = 0; mt < 2; mt++)
#pragma unroll
        for (int nt = 0; nt < 4; nt++) {
            int row0 = wm * 32 + mt * 16 + (lane >> 2);
            int j0 = wn * 32 + nt * 8 + (lane & 3) * 2;
            float v0 = fmaxf(C[mt][nt][0] + B1s[j0], 0.0f);
            float v1 = fmaxf(C[mt][nt][1] + B1s[j0 + 1], 0.0f);
            float v2 = fmaxf(C[mt][nt][2] + B1s[j0], 0.0f);
            float v3 = fmaxf(C[mt][nt][3] + B1s[j0 + 1], 0.0f);
            u32 oa = SWZ((u32)(row0 * 128 + j0 * 2));
            u32 ob = SWZ((u32)((row0 + 8) * 128 + j0 * 2));
            store_split(sm, SM_GH + oa, SM_GL + oa, v0, v1);
            store_split(sm, SM_GH + ob, SM_GL + ob, v2, v3);
        }
    __syncthreads();

    // ================= LAYER 2 (K=64, N=32) =================
#pragma unroll
    for (int mt = 0; mt < 2; mt++)
#pragma unroll
        for (int nt = 0; nt < 2; nt++)
#pragma unroll
            for (int q = 0; q < 4; q++) C[mt][nt][q] = 0.0f;

#pragma unroll
    for (int mt = 0; mt < 2; mt++) {
        int arow = wm * 32 + mt * 16 + arow_off;
        u32 arb = (u32)(arow * 128);
        int ar7 = arow & 7;
        u32 ah[4][4], al[4][4];
#pragma unroll
        for (int kt = 0; kt < 4; kt++) {
            u32 off = arb + (u32)(((2 * kt + akoff) ^ ar7) << 4);
            ldmA(ah[kt], smb + SM_GH + off);
            ldmA(al[kt], smb + SM_GL + off);
        }
#pragma unroll
        for (int nt = 0; nt < 2; nt++) {
            int bn = wn * 16 + nt * 8 + bmr;
            u32 bnb = (u32)(bn * 128);
            int bn7 = bn & 7;
            u32 bh[4][2], bl[4][2];
#pragma unroll
            for (int kt = 0; kt < 4; kt++) {
                u32 off = bnb + (u32)(((2 * kt + bmat) ^ bn7) << 4);
                ldmB(bh[kt], smb + SM_W2H + off);
                ldmB(bl[kt], smb + SM_W2L + off);
            }
#pragma unroll
            for (int kt = 0; kt < 4; kt++) {
                mma16816(C[mt][nt], ah[kt], bh[kt]);
                mma16816(C[mt][nt], ah[kt], bl[kt]);
                mma16816(C[mt][nt], al[kt], bh[kt]);
            }
        }
    }

    // final epilogue: bias, scatter fp32 rows to gmem
#pragma unroll
    for (int mt = 0; mt < 2; mt++)
#pragma unroll
        for (int nt = 0; nt < 2; nt++) {
            int row0 = wm * 32 + mt * 16 + (lane >> 2);
            int j0 = wn * 16 + nt * 8 + (lane & 3) * 2;
            float o0 = C[mt][nt][0] + B2s[j0];
            float o1 = C[mt][nt][1] + B2s[j0 + 1];
            float o2 = C[mt][nt][2] + B2s[j0];
            float o3 = C[mt][nt][3] + B2s[j0 + 1];
            if (row0 < cnt)
                *(float2*)(out + (size_t)sids[row0] * DOUT + j0) = make_float2(o0, o1);
            if (row0 + 8 < cnt)
                *(float2*)(out + (size_t)sids[row0 + 8] * DOUT + j0) = make_float2(o2, o3);
        }
}

// ---------------- launch ----------------
extern "C" void kernel_launch(void* const* d_in, const int* in_sizes, int n_in,
                              void* d_out, int out_size) {
    (void)in_sizes; (void)n_in; (void)out_size;
    const int*   idxs      = (const int*)d_in[0];
    const float* positions = (const float*)d_in[1];
    const float* viewdirs  = (const float*)d_in[2];
    const float* features  = (const float*)d_in[3];
    const float* W0 = (const float*)d_in[4];
    const float* b0 = (const float*)d_in[5];
    const float* W1 = (const float*)d_in[6];
    const float* b1 = (const float*)d_in[7];
    const float* W2 = (const float*)d_in[8];
    const float* b2 = (const float*)d_in[9];
    float* out = (float*)d_out;

    cudaFuncSetAttribute(k_mlp, cudaFuncAttributeMaxDynamicSharedMemorySize, SMEM_BYTES);

    k_hist<<<NSCAT, 256>>>(idxs);
    k_scan<<<1, 1>>>();
    k_scatter<<<NSCAT, 256>>>(idxs);
    k_mlp<<<MAXTILES, NT, SMEM_BYTES>>>(positions, viewdirs, features,
                                        W0, b0, W1, b1, W2, b2, out);
}

// round 8
// speedup vs baseline: 1.1179x; 1.1179x over previous
#include <cuda_runtime.h>
#include <cuda_bf16.h>

typedef unsigned int u32;

// ---------------- problem constants ----------------
#define NS    65536
#define KEXP  8
#define DIN   74
#define WID   64
#define DOUT  32
#define TILE  128
#define NT    256
#define MAXTILES (NS / TILE + KEXP)
#define NSCAT 256

// ---------------- smem layout (bytes) ----------------
#define SM_XH0  0                  // X/H hi: [128 rows][128B] (k 0..63)
#define SM_XL0  16384
#define SM_XH1  32768              // X hi tail: [128 rows][48B] (k 64..79)
#define SM_XL1  38912
#define SM_W0H  45056              // W0 hi, natural k-major: [64 k][128B]
#define SM_W0HT 53248              // W0 hi tail: [16 k][128B]
#define SM_W0L  55296
#define SM_W0LT 63488
#define SM_W1H  65536              // W1 hi: [64 k][128B]
#define SM_W1L  73728
#define SM_GH   45056              // layer-2 input overlays dead W0/W1 region (16KB)
#define SM_GL   61440              // (16KB; ends 77824)
#define SM_W2H  81920              // W2 hi, natural: [64 k][128B] (32 n -> 64B used)
#define SM_W2L  90112
#define SM_B0   98304
#define SM_B1   98560
#define SM_B2   98816
#define SM_SIDS 98944
#define SMEM_BYTES (SM_SIDS + TILE * 4)   // 99456 -> 2 CTAs/SM

#define SWZ(off) ((off) ^ (((off) >> 3) & 0x70))

// ---------------- device scratch ----------------
__device__ int g_hist[KEXP];
__device__ int g_offs[KEXP + 1];
__device__ int g_cursor[KEXP];
__device__ int g_order[NS];

// ---------------- bucketing ----------------
__global__ void k_hist(const int* __restrict__ idxs) {
    __shared__ int sh[KEXP];
    if (threadIdx.x < KEXP) sh[threadIdx.x] = 0;
    __syncthreads();
    atomicAdd(&sh[idxs[blockIdx.x * 256 + threadIdx.x]], 1);
    __syncthreads();
    if (threadIdx.x < KEXP) atomicAdd(&g_hist[threadIdx.x], sh[threadIdx.x]);
}
__global__ void k_scan() {
    int acc = 0;
    for (int e = 0; e < KEXP; e++) {
        g_offs[e] = acc; g_cursor[e] = acc;
        acc += g_hist[e];
        g_hist[e] = 0;
    }
    g_offs[KEXP] = acc;
}
__global__ void k_scatter(const int* __restrict__ idxs) {
    __shared__ int s_loc[KEXP];
    __shared__ int s_base[KEXP];
    if (threadIdx.x < KEXP) s_loc[threadIdx.x] = 0;
    __syncthreads();
    int i = blockIdx.x * 256 + threadIdx.x;
    int e = idxs[i];
    int r = atomicAdd(&s_loc[e], 1);
    __syncthreads();
    if (threadIdx.x < KEXP)
        s_base[threadIdx.x] = atomicAdd(&g_cursor[threadIdx.x], s_loc[threadIdx.x]);
    __syncthreads();
    g_order[s_base[e] + r] = i;
}

// ---------------- PTX helpers (baseline ISA only) ----------------
__device__ __forceinline__ u32 smem_u32(const void* p) {
    u32 a; asm("{ .reg .u64 t; cvta.to.shared.u64 t, %1; cvt.u32.u64 %0, t; }" : "=r"(a) : "l"(p));
    return a;
}
__device__ __forceinline__ void ldmA(u32 a[4], u32 addr) {
    asm volatile("ldmatrix.sync.aligned.m8n8.x4.shared.b16 {%0,%1,%2,%3}, [%4];"
                 : "=r"(a[0]), "=r"(a[1]), "=r"(a[2]), "=r"(a[3]) : "r"(addr));
}
// transposed B-fragment load from natural k-major panels
__device__ __forceinline__ void ldmBT(u32 b[2], u32 addr) {
    asm volatile("ldmatrix.sync.aligned.m8n8.x2.trans.shared.b16 {%0,%1}, [%2];"
                 : "=r"(b[0]), "=r"(b[1]) : "r"(addr));
}
__device__ __forceinline__ void mma16816(float c[4], const u32 a[4], const u32 b[2]) {
    asm volatile(
        "mma.sync.aligned.m16n8k16.row.col.f32.bf16.bf16.f32 "
        "{%0,%1,%2,%3}, {%4,%5,%6,%7}, {%8,%9}, {%0,%1,%2,%3};"
        : "+f"(c[0]), "+f"(c[1]), "+f"(c[2]), "+f"(c[3])
        : "r"(a[0]), "r"(a[1]), "r"(a[2]), "r"(a[3]), "r"(b[0]), "r"(b[1]));
}
__device__ __forceinline__ u32 bpack(__nv_bfloat16 a, __nv_bfloat16 b) {
    __nv_bfloat162 t(a, b);
    return *reinterpret_cast<u32*>(&t);
}
__device__ __forceinline__ void store_split(char* sm, u32 offH, u32 offL, float v0, float v1) {
    __nv_bfloat16 h0 = __float2bfloat16(v0), h1 = __float2bfloat16(v1);
    float l0 = v0 - __bfloat162float(h0), l1 = v1 - __bfloat162float(h1);
    *(u32*)(sm + offH) = bpack(h0, h1);
    *(u32*)(sm + offL) = bpack(__float2bfloat16(l0), __float2bfloat16(l1));
}
// split a float4 (4 consecutive k or n entries) into 2 hi-u32 + 2 lo-u32
__device__ __forceinline__ void split4(float4 v, u32& h01, u32& h23, u32& l01, u32& l23) {
    __nv_bfloat16 hx = __float2bfloat16(v.x), hy = __float2bfloat16(v.y);
    __nv_bfloat16 hz = __float2bfloat16(v.z), hw = __float2bfloat16(v.w);
    h01 = bpack(hx, hy); h23 = bpack(hz, hw);
    l01 = bpack(__float2bfloat16(v.x - __bfloat162float(hx)),
                __float2bfloat16(v.y - __bfloat162float(hy)));
    l23 = bpack(__float2bfloat16(v.z - __bfloat162float(hz)),
                __float2bfloat16(v.w - __bfloat162float(hw)));
}

// ---------------- fused MMA MLP kernel ----------------
__global__ void __launch_bounds__(NT, 2) k_mlp(
    const float* __restrict__ positions, const float* __restrict__ viewdirs,
    const float* __restrict__ features,
    const float* __restrict__ W0g, const float* __restrict__ b0g,
    const float* __restrict__ W1g, const float* __restrict__ b1g,
    const float* __restrict__ W2g, const float* __restrict__ b2g,
    float* __restrict__ out) {
    extern __shared__ char sm[];
    const u32 smb = smem_u32(sm);
    const int tid = threadIdx.x, lane = tid & 31, wid = tid >> 5;

    // blockIdx -> (expert, local tile)
    int e = -1, lt = 0;
    {
        int b = blockIdx.x, acc = 0;
#pragma unroll
        for (int i = 0; i < KEXP; i++) {
            int tiles = (g_offs[i + 1] - g_offs[i] + TILE - 1) / TILE;
            if (e < 0 && b < acc + tiles) { e = i; lt = b - acc; }
            acc += tiles;
        }
    }
    if (e < 0) return;
    const int base = g_offs[e] + lt * TILE;
    const int cnt = min(TILE, g_offs[e + 1] - base);

    int* sids = (int*)(sm + SM_SIDS);
    float* B0s = (float*)(sm + SM_B0);
    float* B1s = (float*)(sm + SM_B1);
    float* B2s = (float*)(sm + SM_B2);

    // ================= STAGING =================
    if (tid < TILE) {
        int n = g_order[base + min(tid, cnt - 1)];   // pad partial tiles with a valid row
        sids[tid] = n;
        float x[80];
        const float4* f4 = (const float4*)(features + (size_t)n * 32);
#pragma unroll
        for (int i = 0; i < 8; i++) {
            float4 f = f4[i];
            x[4 * i] = f.x; x[4 * i + 1] = f.y; x[4 * i + 2] = f.z; x[4 * i + 3] = f.w;
        }
        float p0 = positions[n * 3], p1 = positions[n * 3 + 1], p2 = positions[n * 3 + 2];
        x[32] = p0; x[33] = p1; x[34] = p2;
#pragma unroll
        for (int s = 0; s < 2; s++) {
            float sc = (float)(1 << s);
            x[35 + 3 * s] = __sinf(p0 * sc); x[36 + 3 * s] = __sinf(p1 * sc); x[37 + 3 * s] = __sinf(p2 * sc);
            x[41 + 3 * s] = __cosf(p0 * sc); x[42 + 3 * s] = __cosf(p1 * sc); x[43 + 3 * s] = __cosf(p2 * sc);
        }
        float q0 = viewdirs[n * 3], q1 = viewdirs[n * 3 + 1], q2 = viewdirs[n * 3 + 2];
        x[47] = q0; x[48] = q1; x[49] = q2;
#pragma unroll
        for (int s = 0; s < 4; s++) {
            float sc = (float)(1 << s);
            x[50 + 3 * s] = __sinf(q0 * sc); x[51 + 3 * s] = __sinf(q1 * sc); x[52 + 3 * s] = __sinf(q2 * sc);
            x[62 + 3 * s] = __cosf(q0 * sc); x[63 + 3 * s] = __cosf(q1 * sc); x[64 + 3 * s] = __cosf(q2 * sc);
        }
#pragma unroll
        for (int k = DIN; k < 80; k++) x[k] = 0.0f;
#pragma unroll
        for (int j = 0; j < 40; j++) {
            if (j < 32) {
                u32 off = SWZ((u32)(tid * 128 + j * 4));
                store_split(sm, SM_XH0 + off, SM_XL0 + off, x[2 * j], x[2 * j + 1]);
            } else {
                u32 off = (u32)(tid * 48 + (j - 32) * 4);
                store_split(sm, SM_XH1 + off, SM_XL1 + off, x[2 * j], x[2 * j + 1]);
            }
        }
    } else {
        int t2 = tid - TILE;   // 0..127
        // ---- W0: natural [k][64] rows (256B global, 128B bf16) ----
        const float4* W0e = (const float4*)(W0g + e * DIN * WID);
        for (int i = t2; i < 80 * 16; i += 128) {
            int k = i >> 4, cq = i & 15;
            float4 v = (k < DIN) ? W0e[k * 16 + cq] : make_float4(0.f, 0.f, 0.f, 0.f);
            u32 h01, h23, l01, l23; split4(v, h01, h23, l01, l23);
            u32 bH, bL;
            if (k < 64) { bH = SM_W0H;  bL = SM_W0L;  }
            else        { bH = SM_W0HT; bL = SM_W0LT; k -= 64; }
            u32 off = SWZ((u32)(k * 128 + cq * 8));
            *(u32*)(sm + bH + off) = h01; *(u32*)(sm + bH + off + 4) = h23;
            *(u32*)(sm + bL + off) = l01; *(u32*)(sm + bL + off + 4) = l23;
        }
        // ---- W1: natural [k][64] ----
        const float4* W1e = (const float4*)(W1g + e * WID * WID);
        for (int i = t2; i < 64 * 16; i += 128) {
            int k = i >> 4, cq = i & 15;
            float4 v = W1e[k * 16 + cq];
            u32 h01, h23, l01, l23; split4(v, h01, h23, l01, l23);
            u32 off = SWZ((u32)(k * 128 + cq * 8));
            *(u32*)(sm + SM_W1H + off) = h01; *(u32*)(sm + SM_W1H + off + 4) = h23;
            *(u32*)(sm + SM_W1L + off) = l01; *(u32*)(sm + SM_W1L + off + 4) = l23;
        }
        // ---- W2: natural [k][32] (rows padded to 128B in smem) ----
        const float4* W2e = (const float4*)(W2g + e * WID * DOUT);
        for (int i = t2; i < 64 * 8; i += 128) {
            int k = i >> 3, cq = i & 7;
            float4 v = W2e[k * 8 + cq];
            u32 h01, h23, l01, l23; split4(v, h01, h23, l01, l23);
            u32 off = SWZ((u32)(k * 128 + cq * 8));
            *(u32*)(sm + SM_W2H + off) = h01; *(u32*)(sm + SM_W2H + off + 4) = h23;
            *(u32*)(sm + SM_W2L + off) = l01; *(u32*)(sm + SM_W2L + off + 4) = l23;
        }
        if (t2 < WID) { B0s[t2] = b0g[e * WID + t2]; B1s[t2] = b1g[e * WID + t2]; }
        if (t2 >= WID && t2 < WID + DOUT) B2s[t2 - WID] = b2g[e * DOUT + t2 - WID];
    }
    __syncthreads();

    // fragment lane coordinates (warp grid: 4 M-groups x 2 N-groups)
    const int wm = wid >> 1, wn = wid & 1;
    const int amat = lane >> 3, amr = lane & 7;
    const int arow_off = ((amat & 1) << 3) + amr;
    const int akoff = amat >> 1;
    const int bmr = lane & 7, bmat = (lane >> 3) & 1;   // trans-B: k = 16kt + 8*bmat + bmr

    float C[2][4][4];

    // ================= LAYER 0 (K=80, N=64) =================
#pragma unroll
    for (int mt = 0; mt < 2; mt++)
#pragma unroll
        for (int nt = 0; nt < 4; nt++)
#pragma unroll
            for (int q = 0; q < 4; q++) C[mt][nt][q] = 0.0f;

#pragma unroll
    for (int mt = 0; mt < 2; mt++) {
        int arow = wm * 32 + mt * 16 + arow_off;
        u32 arb = (u32)(arow * 128);
        int ar7 = arow & 7;
        u32 ah[5][4], al[5][4];
#pragma unroll
        for (int kt = 0; kt < 4; kt++) {
            u32 off = arb + (u32)(((2 * kt + akoff) ^ ar7) << 4);
            ldmA(ah[kt], smb + SM_XH0 + off);
            ldmA(al[kt], smb + SM_XL0 + off);
        }
        {
            u32 off = (u32)(arow * 48 + (akoff << 4));
            ldmA(ah[4], smb + SM_XH1 + off);
            ldmA(al[4], smb + SM_XL1 + off);
        }
#pragma unroll
        for (int nt = 0; nt < 4; nt++) {
            int n0 = wn * 32 + nt * 8;
            u32 bh[5][2], bl[5][2];
#pragma unroll
            for (int kt = 0; kt < 4; kt++) {
                int k = 16 * kt + 8 * bmat + bmr;
                u32 off = SWZ((u32)(k * 128 + n0 * 2));
                ldmBT(bh[kt], smb + SM_W0H + off);
                ldmBT(bl[kt], smb + SM_W0L + off);
            }
            {
                int k = 8 * bmat + bmr;   // rows 0..15 of tail panel (k 64..79)
                u32 off = SWZ((u32)(k * 128 + n0 * 2));
                ldmBT(bh[4], smb + SM_W0HT + off);
                ldmBT(bl[4], smb + SM_W0LT + off);
            }
#pragma unroll
            for (int kt = 0; kt < 5; kt++) {
                mma16816(C[mt][nt], ah[kt], bh[kt]);
                mma16816(C[mt][nt], ah[kt], bl[kt]);
                mma16816(C[mt][nt], al[kt], bh[kt]);
            }
        }
    }
    __syncthreads();   // all warps done reading X before H overwrites panel0

    // epilogue L0: bias+relu, split, write H into XH0/XL0
#pragma unroll
    for (int mt = 0; mt < 2; mt++)
#pragma unroll
        for (int nt = 0; nt < 4; nt++) {
            int row0 = wm * 32 + mt * 16 + (lane >> 2);
            int j0 = wn * 32 + nt * 8 + (lane & 3) * 2;
            float v0 = fmaxf(C[mt][nt][0] + B0s[j0], 0.0f);
            float v1 = fmaxf(C[mt][nt][1] + B0s[j0 + 1], 0.0f);
            float v2 = fmaxf(C[mt][nt][2] + B0s[j0], 0.0f);
            float v3 = fmaxf(C[mt][nt][3] + B0s[j0 + 1], 0.0f);
            u32 oa = SWZ((u32)(row0 * 128 + j0 * 2));
            u32 ob = SWZ((u32)((row0 + 8) * 128 + j0 * 2));
            store_split(sm, SM_XH0 + oa, SM_XL0 + oa, v0, v1);
            store_split(sm, SM_XH0 + ob, SM_XL0 + ob, v2, v3);
        }
    __syncthreads();

    // ================= LAYER 1 (K=64, N=64) =================
#pragma unroll
    for (int mt = 0; mt < 2; mt++)
#pragma unroll
        for (int nt = 0; nt < 4; nt++)
#pragma unroll
            for (int q = 0; q < 4; q++) C[mt][nt][q] = 0.0f;

#pragma unroll
    for (int mt = 0; mt < 2; mt++) {
        int arow = wm * 32 + mt * 16 + arow_off;
        u32 arb = (u32)(arow * 128);
        int ar7 = arow & 7;
        u32 ah[4][4], al[4][4];
#pragma unroll
        for (int kt = 0; kt < 4; kt++) {
            u32 off = arb + (u32)(((2 * kt + akoff) ^ ar7) << 4);
            ldmA(ah[kt], smb + SM_XH0 + off);
            ldmA(al[kt], smb + SM_XL0 + off);
        }
#pragma unroll
        for (int nt = 0; nt < 4; nt++) {
            int n0 = wn * 32 + nt * 8;
            u32 bh[4][2], bl[4][2];
#pragma unroll
            for (int kt = 0; kt < 4; kt++) {
                int k = 16 * kt + 8 * bmat + bmr;
                u32 off = SWZ((u32)(k * 128 + n0 * 2));
                ldmBT(bh[kt], smb + SM_W1H + off);
                ldmBT(bl[kt], smb + SM_W1L + off);
            }
#pragma unroll
            for (int kt = 0; kt < 4; kt++) {
                mma16816(C[mt][nt], ah[kt], bh[kt]);
                mma16816(C[mt][nt], ah[kt], bl[kt]);
                mma16816(C[mt][nt], al[kt], bh[kt]);
            }
        }
    }
    __syncthreads();   // done reading W1 region before G overwrites it

    // epilogue L1: bias+relu, split, write G (overlays W0/W1 region)
#pragma unroll
    for (int mt = 0; mt < 2; mt++)
#pragma unroll
        for (int nt = 0; nt < 4; nt++) {
            int row0 = wm * 32 + mt * 16 + (lane >> 2);
            int j0 = wn * 32 + nt * 8 + (lane & 3) * 2;
            float v0 = fmaxf(C[mt][nt][0] + B1s[j0], 0.0f);
            float v1 = fmaxf(C[mt][nt][1] + B1s[j0 + 1], 0.0f);
            float v2 = fmaxf(C[mt][nt][2] + B1s[j0], 0.0f);
            float v3 = fmaxf(C[mt][nt][3] + B1s[j0 + 1], 0.0f);
            u32 oa = SWZ((u32)(row0 * 128 + j0 * 2));
            u32 ob = SWZ((u32)((row0 + 8) * 128 + j0 * 2));
            store_split(sm, SM_GH + oa, SM_GL + oa, v0, v1);
            store_split(sm, SM_GH + ob, SM_GL + ob, v2, v3);
        }
    __syncthreads();

    // ================= LAYER 2 (K=64, N=32) =================
#pragma unroll
    for (int mt = 0; mt < 2; mt++)
#pragma unroll
        for (int nt = 0; nt < 2; nt++)
#pragma unroll
            for (int q = 0; q < 4; q++) C[mt][nt][q] = 0.0f;

#pragma unroll
    for (int mt = 0; mt < 2; mt++) {
        int arow = wm * 32 + mt * 16 + arow_off;
        u32 arb = (u32)(arow * 128);
        int ar7 = arow & 7;
        u32 ah[4][4], al[4][4];
#pragma unroll
        for (int kt = 0; kt < 4; kt++) {
            u32 off = arb + (u32)(((2 * kt + akoff) ^ ar7) << 4);
            ldmA(ah[kt], smb + SM_GH + off);
            ldmA(al[kt], smb + SM_GL + off);
        }
#pragma unroll
        for (int nt = 0; nt < 2; nt++) {
            int n0 = wn * 16 + nt * 8;
            u32 bh[4][2], bl[4][2];
#pragma unroll
            for (int kt = 0; kt < 4; kt++) {
                int k = 16 * kt + 8 * bmat + bmr;
                u32 off = SWZ((u32)(k * 128 + n0 * 2));
                ldmBT(bh[kt], smb + SM_W2H + off);
                ldmBT(bl[kt], smb + SM_W2L + off);
            }
#pragma unroll
            for (int kt = 0; kt < 4; kt++) {
                mma16816(C[mt][nt], ah[kt], bh[kt]);
                mma16816(C[mt][nt], ah[kt], bl[kt]);
                mma16816(C[mt][nt], al[kt], bh[kt]);
            }
        }
    }

    // final epilogue: bias + shuffle-coalesced float4 scatter
#pragma unroll
    for (int mt = 0; mt < 2; mt++)
#pragma unroll
        for (int nt = 0; nt < 2; nt++) {
            int row0 = wm * 32 + mt * 16 + (lane >> 2);
            int q = lane & 3;
            int j0 = wn * 16 + nt * 8 + 2 * q;
            float a0 = C[mt][nt][0] + B2s[j0];
            float a1 = C[mt][nt][1] + B2s[j0 + 1];
            float b0 = C[mt][nt][2] + B2s[j0];
            float b1 = C[mt][nt][3] + B2s[j0 + 1];
            // partner (q^1) sends its pair; even q stores float4 covering 4 cols
            float pa0 = __shfl_xor_sync(0xFFFFFFFFu, a0, 1);
            float pa1 = __shfl_xor_sync(0xFFFFFFFFu, a1, 1);
            float pb0 = __shfl_xor_sync(0xFFFFFFFFu, b0, 1);
            float pb1 = __shfl_xor_sync(0xFFFFFFFFu, b1, 1);
            if (!(q & 1)) {
                int colb = wn * 16 + nt * 8 + 2 * q;   // q=0 -> +0, q=2 -> +4
                if (row0 < cnt)
                    *(float4*)(out + (size_t)sids[row0] * DOUT + colb) =
                        make_float4(a0, a1, pa0, pa1);
                if (row0 + 8 < cnt)
                    *(float4*)(out + (size_t)sids[row0 + 8] * DOUT + colb) =
                        make_float4(b0, b1, pb0, pb1);
            }
        }
}

// ---------------- launch ----------------
extern "C" void kernel_launch(void* const* d_in, const int* in_sizes, int n_in,
                              void* d_out, int out_size) {
    (void)in_sizes; (void)n_in; (void)out_size;
    const int*   idxs      = (const int*)d_in[0];
    const float* positions = (const float*)d_in[1];
    const float* viewdirs  = (const float*)d_in[2];
    const float* features  = (const float*)d_in[3];
    const float* W0 = (const float*)d_in[4];
    const float* b0 = (const float*)d_in[5];
    const float* W1 = (const float*)d_in[6];
    const float* b1 = (const float*)d_in[7];
    const float* W2 = (const float*)d_in[8];
    const float* b2 = (const float*)d_in[9];
    float* out = (float*)d_out;

    cudaFuncSetAttribute(k_mlp, cudaFuncAttributeMaxDynamicSharedMemorySize, SMEM_BYTES);

    k_hist<<<NSCAT, 256>>>(idxs);
    k_scan<<<1, 1>>>();
    k_scatter<<<NSCAT, 256>>>(idxs);
    k_mlp<<<MAXTILES, NT, SMEM_BYTES>>>(positions, viewdirs, features,
                                        W0, b0, W1, b1, W2, b2, out);
}

// round 9
// speedup vs baseline: 1.1284x; 1.0095x over previous
#include <cuda_runtime.h>
#include <cuda_bf16.h>

typedef unsigned int u32;

// ---------------- problem constants ----------------
#define NS    65536
#define KEXP  8
#define DIN   74
#define WID   64
#define DOUT  32
#define TILE  128
#define NT    256
#define MAXTILES (NS / TILE + KEXP)
#define NSCAT 256

// ---------------- smem layout (bytes) ----------------
#define SM_XH0  0                  // X/H hi: [128 rows][128B] (k 0..63)
#define SM_XL0  16384
#define SM_XH1  32768              // X hi tail: [128 rows][48B] (k 64..79)
#define SM_XL1  38912
#define SM_W0H  45056              // W0 hi, natural k-major: [64 k][128B]
#define SM_W0HT 53248              // W0 hi tail: [16 k][128B]
#define SM_W0L  55296
#define SM_W0LT 63488
#define SM_W1H  65536              // W1 hi: [64 k][128B]
#define SM_W1L  73728
#define SM_GH   45056              // layer-2 input overlays dead W0/W1 region (16KB)
#define SM_GL   61440              // (16KB; ends 77824)
#define SM_W2H  81920              // W2 hi, natural: [64 k][128B] (32 n -> 64B used)
#define SM_W2L  90112
#define SM_B0   98304
#define SM_B1   98560
#define SM_B2   98816
#define SM_SIDS 98944
#define SMEM_BYTES (SM_SIDS + TILE * 4)   // 99456 -> 2 CTAs/SM

#define SWZ(off) ((off) ^ (((off) >> 3) & 0x70))

// ---------------- device scratch ----------------
__device__ int g_hist[KEXP];
__device__ int g_offs[KEXP + 1];
__device__ int g_cursor[KEXP];
__device__ int g_order[NS];

// ---------------- bucketing ----------------
__global__ void k_hist(const int* __restrict__ idxs) {
    __shared__ int sh[KEXP];
    if (threadIdx.x < KEXP) sh[threadIdx.x] = 0;
    __syncthreads();
    atomicAdd(&sh[idxs[blockIdx.x * 256 + threadIdx.x]], 1);
    __syncthreads();
    if (threadIdx.x < KEXP) atomicAdd(&g_hist[threadIdx.x], sh[threadIdx.x]);
}
__global__ void k_scan() {
    int acc = 0;
    for (int e = 0; e < KEXP; e++) {
        g_offs[e] = acc; g_cursor[e] = acc;
        acc += g_hist[e];
        g_hist[e] = 0;
    }
    g_offs[KEXP] = acc;
}
__global__ void k_scatter(const int* __restrict__ idxs) {
    __shared__ int s_loc[KEXP];
    __shared__ int s_base[KEXP];
    if (threadIdx.x < KEXP) s_loc[threadIdx.x] = 0;
    __syncthreads();
    int i = blockIdx.x * 256 + threadIdx.x;
    int e = idxs[i];
    int r = atomicAdd(&s_loc[e], 1);
    __syncthreads();
    if (threadIdx.x < KEXP)
        s_base[threadIdx.x] = atomicAdd(&g_cursor[threadIdx.x], s_loc[threadIdx.x]);
    __syncthreads();
    g_order[s_base[e] + r] = i;
}

// ---------------- PTX helpers (baseline ISA only) ----------------
__device__ __forceinline__ u32 smem_u32(const void* p) {
    u32 a; asm("{ .reg .u64 t; cvta.to.shared.u64 t, %1; cvt.u32.u64 %0, t; }" : "=r"(a) : "l"(p));
    return a;
}
__device__ __forceinline__ void ldmA(u32 a[4], u32 addr) {
    asm volatile("ldmatrix.sync.aligned.m8n8.x4.shared.b16 {%0,%1,%2,%3}, [%4];"
                 : "=r"(a[0]), "=r"(a[1]), "=r"(a[2]), "=r"(a[3]) : "r"(addr));
}
// x4 transposed B load: one instruction = k16 x n16 (two n8 fragments)
__device__ __forceinline__ void ldmBT4(u32 b[4], u32 addr) {
    asm volatile("ldmatrix.sync.aligned.m8n8.x4.trans.shared.b16 {%0,%1,%2,%3}, [%4];"
                 : "=r"(b[0]), "=r"(b[1]), "=r"(b[2]), "=r"(b[3]) : "r"(addr));
}
__device__ __forceinline__ void mma16816(float c[4], const u32 a[4], const u32 b[2]) {
    asm volatile(
        "mma.sync.aligned.m16n8k16.row.col.f32.bf16.bf16.f32 "
        "{%0,%1,%2,%3}, {%4,%5,%6,%7}, {%8,%9}, {%0,%1,%2,%3};"
        : "+f"(c[0]), "+f"(c[1]), "+f"(c[2]), "+f"(c[3])
        : "r"(a[0]), "r"(a[1]), "r"(a[2]), "r"(a[3]), "r"(b[0]), "r"(b[1]));
}
__device__ __forceinline__ u32 bpack(__nv_bfloat16 a, __nv_bfloat16 b) {
    __nv_bfloat162 t(a, b);
    return *reinterpret_cast<u32*>(&t);
}
__device__ __forceinline__ void store_split(char* sm, u32 offH, u32 offL, float v0, float v1) {
    __nv_bfloat16 h0 = __float2bfloat16(v0), h1 = __float2bfloat16(v1);
    float l0 = v0 - __bfloat162float(h0), l1 = v1 - __bfloat162float(h1);
    *(u32*)(sm + offH) = bpack(h0, h1);
    *(u32*)(sm + offL) = bpack(__float2bfloat16(l0), __float2bfloat16(l1));
}
__device__ __forceinline__ void split4(float4 v, u32& h01, u32& h23, u32& l01, u32& l23) {
    __nv_bfloat16 hx = __float2bfloat16(v.x), hy = __float2bfloat16(v.y);
    __nv_bfloat16 hz = __float2bfloat16(v.z), hw = __float2bfloat16(v.w);
    h01 = bpack(hx, hy); h23 = bpack(hz, hw);
    l01 = bpack(__float2bfloat16(v.x - __bfloat162float(hx)),
                __float2bfloat16(v.y - __bfloat162float(hy)));
    l23 = bpack(__float2bfloat16(v.z - __bfloat162float(hz)),
                __float2bfloat16(v.w - __bfloat162float(hw)));
}

// ---------------- fused MMA MLP kernel ----------------
__global__ void __launch_bounds__(NT, 2) k_mlp(
    const float* __restrict__ positions, const float* __restrict__ viewdirs,
    const float* __restrict__ features,
    const float* __restrict__ W0g, const float* __restrict__ b0g,
    const float* __restrict__ W1g, const float* __restrict__ b1g,
    const float* __restrict__ W2g, const float* __restrict__ b2g,
    float* __restrict__ out) {
    extern __shared__ char sm[];
    const u32 smb = smem_u32(sm);
    const int tid = threadIdx.x, lane = tid & 31, wid = tid >> 5;

    // blockIdx -> (expert, local tile)
    int e = -1, lt = 0;
    {
        int b = blockIdx.x, acc = 0;
#pragma unroll
        for (int i = 0; i < KEXP; i++) {
            int tiles = (g_offs[i + 1] - g_offs[i] + TILE - 1) / TILE;
            if (e < 0 && b < acc + tiles) { e = i; lt = b - acc; }
            acc += tiles;
        }
    }
    if (e < 0) return;
    const int base = g_offs[e] + lt * TILE;
    const int cnt = min(TILE, g_offs[e + 1] - base);

    int* sids = (int*)(sm + SM_SIDS);
    float* B0s = (float*)(sm + SM_B0);
    float* B1s = (float*)(sm + SM_B1);
    float* B2s = (float*)(sm + SM_B2);

    // ================= STAGING =================
    if (tid < TILE) {
        int n = g_order[base + min(tid, cnt - 1)];   // pad partial tiles with a valid row
        sids[tid] = n;
        float x[80];
        const float4* f4 = (const float4*)(features + (size_t)n * 32);
#pragma unroll
        for (int i = 0; i < 8; i++) {
            float4 f = f4[i];
            x[4 * i] = f.x; x[4 * i + 1] = f.y; x[4 * i + 2] = f.z; x[4 * i + 3] = f.w;
        }
        float p0 = positions[n * 3], p1 = positions[n * 3 + 1], p2 = positions[n * 3 + 2];
        x[32] = p0; x[33] = p1; x[34] = p2;
#pragma unroll
        for (int s = 0; s < 2; s++) {
            float sc = (float)(1 << s);
            x[35 + 3 * s] = __sinf(p0 * sc); x[36 + 3 * s] = __sinf(p1 * sc); x[37 + 3 * s] = __sinf(p2 * sc);
            x[41 + 3 * s] = __cosf(p0 * sc); x[42 + 3 * s] = __cosf(p1 * sc); x[43 + 3 * s] = __cosf(p2 * sc);
        }
        float q0 = viewdirs[n * 3], q1 = viewdirs[n * 3 + 1], q2 = viewdirs[n * 3 + 2];
        x[47] = q0; x[48] = q1; x[49] = q2;
#pragma unroll
        for (int s = 0; s < 4; s++) {
            float sc = (float)(1 << s);
            x[50 + 3 * s] = __sinf(q0 * sc); x[51 + 3 * s] = __sinf(q1 * sc); x[52 + 3 * s] = __sinf(q2 * sc);
            x[62 + 3 * s] = __cosf(q0 * sc); x[63 + 3 * s] = __cosf(q1 * sc); x[64 + 3 * s] = __cosf(q2 * sc);
        }
#pragma unroll
        for (int k = DIN; k < 80; k++) x[k] = 0.0f;
#pragma unroll
        for (int j = 0; j < 40; j++) {
            if (j < 32) {
                u32 off = SWZ((u32)(tid * 128 + j * 4));
                store_split(sm, SM_XH0 + off, SM_XL0 + off, x[2 * j], x[2 * j + 1]);
            } else {
                u32 off = (u32)(tid * 48 + (j - 32) * 4);
                store_split(sm, SM_XH1 + off, SM_XL1 + off, x[2 * j], x[2 * j + 1]);
            }
        }
    } else {
        int t2 = tid - TILE;   // 0..127
        const float4* W0e = (const float4*)(W0g + e * DIN * WID);
        for (int i = t2; i < 80 * 16; i += 128) {
            int k = i >> 4, cq = i & 15;
            float4 v = (k < DIN) ? W0e[k * 16 + cq] : make_float4(0.f, 0.f, 0.f, 0.f);
            u32 h01, h23, l01, l23; split4(v, h01, h23, l01, l23);
            u32 bH, bL;
            if (k < 64) { bH = SM_W0H;  bL = SM_W0L;  }
            else        { bH = SM_W0HT; bL = SM_W0LT; k -= 64; }
            u32 off = SWZ((u32)(k * 128 + cq * 8));
            *(u32*)(sm + bH + off) = h01; *(u32*)(sm + bH + off + 4) = h23;
            *(u32*)(sm + bL + off) = l01; *(u32*)(sm + bL + off + 4) = l23;
        }
        const float4* W1e = (const float4*)(W1g + e * WID * WID);
        for (int i = t2; i < 64 * 16; i += 128) {
            int k = i >> 4, cq = i & 15;
            float4 v = W1e[k * 16 + cq];
            u32 h01, h23, l01, l23; split4(v, h01, h23, l01, l23);
            u32 off = SWZ((u32)(k * 128 + cq * 8));
            *(u32*)(sm + SM_W1H + off) = h01; *(u32*)(sm + SM_W1H + off + 4) = h23;
            *(u32*)(sm + SM_W1L + off) = l01; *(u32*)(sm + SM_W1L + off + 4) = l23;
        }
        const float4* W2e = (const float4*)(W2g + e * WID * DOUT);
        for (int i = t2; i < 64 * 8; i += 128) {
            int k = i >> 3, cq = i & 7;
            float4 v = W2e[k * 8 + cq];
            u32 h01, h23, l01, l23; split4(v, h01, h23, l01, l23);
            u32 off = SWZ((u32)(k * 128 + cq * 8));
            *(u32*)(sm + SM_W2H + off) = h01; *(u32*)(sm + SM_W2H + off + 4) = h23;
            *(u32*)(sm + SM_W2L + off) = l01; *(u32*)(sm + SM_W2L + off + 4) = l23;
        }
        if (t2 < WID) { B0s[t2] = b0g[e * WID + t2]; B1s[t2] = b1g[e * WID + t2]; }
        if (t2 >= WID && t2 < WID + DOUT) B2s[t2 - WID] = b2g[e * DOUT + t2 - WID];
    }
    __syncthreads();

    // fragment lane coordinates (warp grid: 4 M-groups x 2 N-groups)
    const int wm = wid >> 1, wn = wid & 1;
    const int amat = lane >> 3, amr = lane & 7;
    const int arow_off = ((amat & 1) << 3) + amr;
    const int akoff = amat >> 1;
    // x4-trans B lane coords: matrix idx = lane>>3; k-half = midx&1, n-half = midx>>1
    const int bk = ((lane >> 3) & 1) * 8 + (lane & 7);
    const int bnh = (lane >> 4) * 8;

    float C[2][4][4];

    // ================= LAYER 0 (K=80, N=64) =================
#pragma unroll
    for (int mt = 0; mt < 2; mt++)
#pragma unroll
        for (int nt = 0; nt < 4; nt++)
#pragma unroll
            for (int q = 0; q < 4; q++) C[mt][nt][q] = 0.0f;

#pragma unroll
    for (int mt = 0; mt < 2; mt++) {
        int arow = wm * 32 + mt * 16 + arow_off;
        u32 arb = (u32)(arow * 128);
        int ar7 = arow & 7;
        u32 ah[5][4], al[5][4];
#pragma unroll
        for (int kt = 0; kt < 4; kt++) {
            u32 off = arb + (u32)(((2 * kt + akoff) ^ ar7) << 4);
            ldmA(ah[kt], smb + SM_XH0 + off);
            ldmA(al[kt], smb + SM_XL0 + off);
        }
        {
            u32 off = (u32)(arow * 48 + (akoff << 4));
            ldmA(ah[4], smb + SM_XH1 + off);
            ldmA(al[4], smb + SM_XL1 + off);
        }
#pragma unroll
        for (int np = 0; np < 2; np++) {
            int n0 = wn * 32 + np * 16 + bnh;
            u32 bh[5][4], bl[5][4];
#pragma unroll
            for (int kt = 0; kt < 4; kt++) {
                u32 off = SWZ((u32)((16 * kt + bk) * 128 + n0 * 2));
                ldmBT4(bh[kt], smb + SM_W0H + off);
                ldmBT4(bl[kt], smb + SM_W0L + off);
            }
            {
                u32 off = SWZ((u32)(bk * 128 + n0 * 2));   // tail panel rows 0..15
                ldmBT4(bh[4], smb + SM_W0HT + off);
                ldmBT4(bl[4], smb + SM_W0LT + off);
            }
#pragma unroll
            for (int kt = 0; kt < 5; kt++)
#pragma unroll
                for (int sub = 0; sub < 2; sub++) {
                    float* c = C[mt][2 * np + sub];
                    mma16816(c, ah[kt], &bh[kt][2 * sub]);
                    mma16816(c, ah[kt], &bl[kt][2 * sub]);
                    mma16816(c, al[kt], &bh[kt][2 * sub]);
                }
        }
    }
    __syncthreads();   // all warps done reading X before H overwrites panel0

    // epilogue L0: bias+relu, split, write H into XH0/XL0
#pragma unroll
    for (int mt = 0; mt < 2; mt++)
#pragma unroll
        for (int nt = 0; nt < 4; nt++) {
            int row0 = wm * 32 + mt * 16 + (lane >> 2);
            int j0 = wn * 32 + nt * 8 + (lane & 3) * 2;
            float v0 = fmaxf(C[mt][nt][0] + B0s[j0], 0.0f);
            float v1 = fmaxf(C[mt][nt][1] + B0s[j0 + 1], 0.0f);
            float v2 = fmaxf(C[mt][nt][2] + B0s[j0], 0.0f);
            float v3 = fmaxf(C[mt][nt][3] + B0s[j0 + 1], 0.0f);
            u32 oa = SWZ((u32)(row0 * 128 + j0 * 2));
            u32 ob = SWZ((u32)((row0 + 8) * 128 + j0 * 2));
            store_split(sm, SM_XH0 + oa, SM_XL0 + oa, v0, v1);
            store_split(sm, SM_XH0 + ob, SM_XL0 + ob, v2, v3);
        }
    __syncthreads();

    // ================= LAYER 1 (K=64, N=64) =================
#pragma unroll
    for (int mt = 0; mt < 2; mt++)
#pragma unroll
        for (int nt = 0; nt < 4; nt++)
#pragma unroll
            for (int q = 0; q < 4; q++) C[mt][nt][q] = 0.0f;

#pragma unroll
    for (int mt = 0; mt < 2; mt++) {
        int arow = wm * 32 + mt * 16 + arow_off;
        u32 arb = (u32)(arow * 128);
        int ar7 = arow & 7;
        u32 ah[4][4], al[4][4];
#pragma unroll
        for (int kt = 0; kt < 4; kt++) {
            u32 off = arb + (u32)(((2 * kt + akoff) ^ ar7) << 4);
            ldmA(ah[kt], smb + SM_XH0 + off);
            ldmA(al[kt], smb + SM_XL0 + off);
        }
#pragma unroll
        for (int np = 0; np < 2; np++) {
            int n0 = wn * 32 + np * 16 + bnh;
            u32 bh[4][4], bl[4][4];
#pragma unroll
            for (int kt = 0; kt < 4; kt++) {
                u32 off = SWZ((u32)((16 * kt + bk) * 128 + n0 * 2));
                ldmBT4(bh[kt], smb + SM_W1H + off);
                ldmBT4(bl[kt], smb + SM_W1L + off);
            }
#pragma unroll
            for (int kt = 0; kt < 4; kt++)
#pragma unroll
                for (int sub = 0; sub < 2; sub++) {
                    float* c = C[mt][2 * np + sub];
                    mma16816(c, ah[kt], &bh[kt][2 * sub]);
                    mma16816(c, ah[kt], &bl[kt][2 * sub]);
                    mma16816(c, al[kt], &bh[kt][2 * sub]);
                }
        }
    }
    __syncthreads();   // done reading W1 region before G overwrites it

    // epilogue L1: bias+relu, split, write G (overlays W0/W1 region)
#pragma unroll
    for (int mt = 0; mt < 2; mt++)
#pragma unroll
        for (int nt = 0; nt < 4; nt++) {
            int row0 = wm * 32 + mt * 16 + (lane >> 2);
            int j0 = wn * 32 + nt * 8 + (lane & 3) * 2;
            float v0 = fmaxf(C[mt][nt][0] + B1s[j0], 0.0f);
            float v1 = fmaxf(C[mt][nt][1] + B1s[j0 + 1], 0.0f);
            float v2 = fmaxf(C[mt][nt][2] + B1s[j0], 0.0f);
            float v3 = fmaxf(C[mt][nt][3] + B1s[j0 + 1], 0.0f);
            u32 oa = SWZ((u32)(row0 * 128 + j0 * 2));
            u32 ob = SWZ((u32)((row0 + 8) * 128 + j0 * 2));
            store_split(sm, SM_GH + oa, SM_GL + oa, v0, v1);
            store_split(sm, SM_GH + ob, SM_GL + ob, v2, v3);
        }
    __syncthreads();

    // ================= LAYER 2 (K=64, N=32) =================
#pragma unroll
    for (int mt = 0; mt < 2; mt++)
#pragma unroll
        for (int nt = 0; nt < 2; nt++)
#pragma unroll
            for (int q = 0; q < 4; q++) C[mt][nt][q] = 0.0f;

#pragma unroll
    for (int mt = 0; mt < 2; mt++) {
        int arow = wm * 32 + mt * 16 + arow_off;
        u32 arb = (u32)(arow * 128);
        int ar7 = arow & 7;
        u32 ah[4][4], al[4][4];
#pragma unroll
        for (int kt = 0; kt < 4; kt++) {
            u32 off = arb + (u32)(((2 * kt + akoff) ^ ar7) << 4);
            ldmA(ah[kt], smb + SM_GH + off);
            ldmA(al[kt], smb + SM_GL + off);
        }
        {
            int n0 = wn * 16 + bnh;
            u32 bh[4][4], bl[4][4];
#pragma unroll
            for (int kt = 0; kt < 4; kt++) {
                u32 off = SWZ((u32)((16 * kt + bk) * 128 + n0 * 2));
                ldmBT4(bh[kt], smb + SM_W2H + off);
                ldmBT4(bl[kt], smb + SM_W2L + off);
            }
#pragma unroll
            for (int kt = 0; kt < 4; kt++)
#pragma unroll
                for (int sub = 0; sub < 2; sub++) {
                    float* c = C[mt][sub];
                    mma16816(c, ah[kt], &bh[kt][2 * sub]);
                    mma16816(c, ah[kt], &bl[kt][2 * sub]);
                    mma16816(c, al[kt], &bh[kt][2 * sub]);
                }
        }
    }

    // final epilogue: bias + shuffle-coalesced float4 scatter
#pragma unroll
    for (int mt = 0; mt < 2; mt++)
#pragma unroll
        for (int nt = 0; nt < 2; nt++) {
            int row0 = wm * 32 + mt * 16 + (lane >> 2);
            int q = lane & 3;
            int j0 = wn * 16 + nt * 8 + 2 * q;
            float a0 = C[mt][nt][0] + B2s[j0];
            float a1 = C[mt][nt][1] + B2s[j0 + 1];
            float b0 = C[mt][nt][2] + B2s[j0];
            float b1 = C[mt][nt][3] + B2s[j0 + 1];
            float pa0 = __shfl_xor_sync(0xFFFFFFFFu, a0, 1);
            float pa1 = __shfl_xor_sync(0xFFFFFFFFu, a1, 1);
            float pb0 = __shfl_xor_sync(0xFFFFFFFFu, b0, 1);
            float pb1 = __shfl_xor_sync(0xFFFFFFFFu, b1, 1);
            if (!(q & 1)) {
                int colb = wn * 16 + nt * 8 + 2 * q;
                if (row0 < cnt)
                    *(float4*)(out + (size_t)sids[row0] * DOUT + colb) =
                        make_float4(a0, a1, pa0, pa1);
                if (row0 + 8 < cnt)
                    *(float4*)(out + (size_t)sids[row0 + 8] * DOUT + colb) =
                        make_float4(b0, b1, pb0, pb1);
            }
        }
}

// ---------------- launch ----------------
extern "C" void kernel_launch(void* const* d_in, const int* in_sizes, int n_in,
                              void* d_out, int out_size) {
    (void)in_sizes; (void)n_in; (void)out_size;
    const int*   idxs      = (const int*)d_in[0];
    const float* positions = (const float*)d_in[1];
    const float* viewdirs  = (const float*)d_in[2];
    const float* features  = (const float*)d_in[3];
    const float* W0 = (const float*)d_in[4];
    const float* b0 = (const float*)d_in[5];
    const float* W1 = (const float*)d_in[6];
    const float* b1 = (const float*)d_in[7];
    const float* W2 = (const float*)d_in[8];
    const float* b2 = (const float*)d_in[9];
    float* out = (float*)d_out;

    cudaFuncSetAttribute(k_mlp, cudaFuncAttributeMaxDynamicSharedMemorySize, SMEM_BYTES);

    k_hist<<<NSCAT, 256>>>(idxs);
    k_scan<<<1, 1>>>();
    k_scatter<<<NSCAT, 256>>>(idxs);
    k_mlp<<<MAXTILES, NT, SMEM_BYTES>>>(positions, viewdirs, features,
                                        W0, b0, W1, b1, W2, b2, out);
}

// round 10
// speedup vs baseline: 1.2983x; 1.1505x over previous
#include <cuda_runtime.h>
#include <cuda_fp16.h>

typedef unsigned int u32;

// ---------------- problem constants ----------------
#define NS    65536
#define KEXP  8
#define DIN   74
#define WID   64
#define DOUT  32
#define TILE  128
#define NT    256
#define MAXTILES (NS / TILE + KEXP)
#define NSCAT 256

// ---------------- smem layout (bytes) ----------------
// X split into fp16 hi/lo panels; W fp16 hi only (2-term split product)
#define SM_XH0  0                  // X/H/G hi: [128 rows][128B] (k 0..63)
#define SM_XL0  16384              // X/H/G lo
#define SM_XH1  32768              // X hi tail: [128 rows][48B] (k 64..79)
#define SM_XL1  38912
#define SM_W0H  45056              // W0 hi, natural k-major: [64 k][128B]
#define SM_W0HT 53248              // W0 hi tail: [16 k][128B]
#define SM_W1H  55296              // W1 hi: [64 k][128B]
#define SM_W2H  63488              // W2 hi: [64 k][128B] (32 n -> 64B used)
#define SM_B0   71680
#define SM_B1   71936
#define SM_B2   72192
#define SM_SIDS 72320
#define SMEM_BYTES (SM_SIDS + TILE * 4)   // 72832 -> 3 CTAs/SM

#define SWZ(off) ((off) ^ (((off) >> 3) & 0x70))

// ---------------- device scratch ----------------
__device__ int g_hist[KEXP];
__device__ int g_offs[KEXP + 1];
__device__ int g_cursor[KEXP];
__device__ int g_order[NS];

// ---------------- bucketing ----------------
__global__ void k_hist(const int* __restrict__ idxs) {
    __shared__ int sh[KEXP];
    if (threadIdx.x < KEXP) sh[threadIdx.x] = 0;
    __syncthreads();
    atomicAdd(&sh[idxs[blockIdx.x * 256 + threadIdx.x]], 1);
    __syncthreads();
    if (threadIdx.x < KEXP) atomicAdd(&g_hist[threadIdx.x], sh[threadIdx.x]);
}
__global__ void k_scan() {
    int acc = 0;
    for (int e = 0; e < KEXP; e++) {
        g_offs[e] = acc; g_cursor[e] = acc;
        acc += g_hist[e];
        g_hist[e] = 0;
    }
    g_offs[KEXP] = acc;
}
__global__ void k_scatter(const int* __restrict__ idxs) {
    __shared__ int s_loc[KEXP];
    __shared__ int s_base[KEXP];
    if (threadIdx.x < KEXP) s_loc[threadIdx.x] = 0;
    __syncthreads();
    int i = blockIdx.x * 256 + threadIdx.x;
    int e = idxs[i];
    int r = atomicAdd(&s_loc[e], 1);
    __syncthreads();
    if (threadIdx.x < KEXP)
        s_base[threadIdx.x] = atomicAdd(&g_cursor[threadIdx.x], s_loc[threadIdx.x]);
    __syncthreads();
    g_order[s_base[e] + r] = i;
}

// ---------------- PTX helpers (baseline ISA only) ----------------
__device__ __forceinline__ u32 smem_u32(const void* p) {
    u32 a; asm("{ .reg .u64 t; cvta.to.shared.u64 t, %1; cvt.u32.u64 %0, t; }" : "=r"(a) : "l"(p));
    return a;
}
__device__ __forceinline__ void ldmA(u32 a[4], u32 addr) {
    asm volatile("ldmatrix.sync.aligned.m8n8.x4.shared.b16 {%0,%1,%2,%3}, [%4];"
                 : "=r"(a[0]), "=r"(a[1]), "=r"(a[2]), "=r"(a[3]) : "r"(addr));
}
// x4 transposed B load: one instruction = k16 x n16 (two n8 fragments)
__device__ __forceinline__ void ldmBT4(u32 b[4], u32 addr) {
    asm volatile("ldmatrix.sync.aligned.m8n8.x4.trans.shared.b16 {%0,%1,%2,%3}, [%4];"
                 : "=r"(b[0]), "=r"(b[1]), "=r"(b[2]), "=r"(b[3]) : "r"(addr));
}
__device__ __forceinline__ void mma16816(float c[4], const u32 a[4], const u32 b[2]) {
    asm volatile(
        "mma.sync.aligned.m16n8k16.row.col.f32.f16.f16.f32 "
        "{%0,%1,%2,%3}, {%4,%5,%6,%7}, {%8,%9}, {%0,%1,%2,%3};"
        : "+f"(c[0]), "+f"(c[1]), "+f"(c[2]), "+f"(c[3])
        : "r"(a[0]), "r"(a[1]), "r"(a[2]), "r"(a[3]), "r"(b[0]), "r"(b[1]));
}
__device__ __forceinline__ u32 hpack(__half a, __half b) {
    __half2 t(a, b);
    return *reinterpret_cast<u32*>(&t);
}
// split (v0,v1) into fp16 hi/lo pairs; store u32 each
__device__ __forceinline__ void store_split(char* sm, u32 offH, u32 offL, float v0, float v1) {
    __half h0 = __float2half_rn(v0), h1 = __float2half_rn(v1);
    float l0 = v0 - __half2float(h0), l1 = v1 - __half2float(h1);
    *(u32*)(sm + offH) = hpack(h0, h1);
    *(u32*)(sm + offL) = hpack(__float2half_rn(l0), __float2half_rn(l1));
}
// W: hi only
__device__ __forceinline__ void split4h(float4 v, u32& h01, u32& h23) {
    h01 = hpack(__float2half_rn(v.x), __float2half_rn(v.y));
    h23 = hpack(__float2half_rn(v.z), __float2half_rn(v.w));
}

// ---------------- fused MMA MLP kernel ----------------
__global__ void __launch_bounds__(NT, 3) k_mlp(
    const float* __restrict__ positions, const float* __restrict__ viewdirs,
    const float* __restrict__ features,
    const float* __restrict__ W0g, const float* __restrict__ b0g,
    const float* __restrict__ W1g, const float* __restrict__ b1g,
    const float* __restrict__ W2g, const float* __restrict__ b2g,
    float* __restrict__ out) {
    extern __shared__ char sm[];
    const u32 smb = smem_u32(sm);
    const int tid = threadIdx.x, lane = tid & 31, wid = tid >> 5;

    // blockIdx -> (expert, local tile)
    int e = -1, lt = 0;
    {
        int b = blockIdx.x, acc = 0;
#pragma unroll
        for (int i = 0; i < KEXP; i++) {
            int tiles = (g_offs[i + 1] - g_offs[i] + TILE - 1) / TILE;
            if (e < 0 && b < acc + tiles) { e = i; lt = b - acc; }
            acc += tiles;
        }
    }
    if (e < 0) return;
    const int base = g_offs[e] + lt * TILE;
    const int cnt = min(TILE, g_offs[e + 1] - base);

    int* sids = (int*)(sm + SM_SIDS);
    float* B0s = (float*)(sm + SM_B0);
    float* B1s = (float*)(sm + SM_B1);
    float* B2s = (float*)(sm + SM_B2);

    // ================= STAGING =================
    if (tid < TILE) {
        int n = g_order[base + min(tid, cnt - 1)];   // pad partial tiles with a valid row
        sids[tid] = n;
        float x[80];
        const float4* f4 = (const float4*)(features + (size_t)n * 32);
#pragma unroll
        for (int i = 0; i < 8; i++) {
            float4 f = f4[i];
            x[4 * i] = f.x; x[4 * i + 1] = f.y; x[4 * i + 2] = f.z; x[4 * i + 3] = f.w;
        }
        float p0 = positions[n * 3], p1 = positions[n * 3 + 1], p2 = positions[n * 3 + 2];
        x[32] = p0; x[33] = p1; x[34] = p2;
#pragma unroll
        for (int s = 0; s < 2; s++) {
            float sc = (float)(1 << s);
            x[35 + 3 * s] = __sinf(p0 * sc); x[36 + 3 * s] = __sinf(p1 * sc); x[37 + 3 * s] = __sinf(p2 * sc);
            x[41 + 3 * s] = __cosf(p0 * sc); x[42 + 3 * s] = __cosf(p1 * sc); x[43 + 3 * s] = __cosf(p2 * sc);
        }
        float q0 = viewdirs[n * 3], q1 = viewdirs[n * 3 + 1], q2 = viewdirs[n * 3 + 2];
        x[47] = q0; x[48] = q1; x[49] = q2;
#pragma unroll
        for (int s = 0; s < 4; s++) {
            float sc = (float)(1 << s);
            x[50 + 3 * s] = __sinf(q0 * sc); x[51 + 3 * s] = __sinf(q1 * sc); x[52 + 3 * s] = __sinf(q2 * sc);
            x[62 + 3 * s] = __cosf(q0 * sc); x[63 + 3 * s] = __cosf(q1 * sc); x[64 + 3 * s] = __cosf(q2 * sc);
        }
#pragma unroll
        for (int k = DIN; k < 80; k++) x[k] = 0.0f;
#pragma unroll
        for (int j = 0; j < 40; j++) {
            if (j < 32) {
                u32 off = SWZ((u32)(tid * 128 + j * 4));
                store_split(sm, SM_XH0 + off, SM_XL0 + off, x[2 * j], x[2 * j + 1]);
            } else {
                u32 off = (u32)(tid * 48 + (j - 32) * 4);
                store_split(sm, SM_XH1 + off, SM_XL1 + off, x[2 * j], x[2 * j + 1]);
            }
        }
    } else {
        int t2 = tid - TILE;   // 0..127
        const float4* W0e = (const float4*)(W0g + e * DIN * WID);
        for (int i = t2; i < 80 * 16; i += 128) {
            int k = i >> 4, cq = i & 15;
            float4 v = (k < DIN) ? W0e[k * 16 + cq] : make_float4(0.f, 0.f, 0.f, 0.f);
            u32 h01, h23; split4h(v, h01, h23);
            u32 bH;
            if (k < 64) { bH = SM_W0H; }
            else        { bH = SM_W0HT; k -= 64; }
            u32 off = SWZ((u32)(k * 128 + cq * 8));
            *(u32*)(sm + bH + off) = h01; *(u32*)(sm + bH + off + 4) = h23;
        }
        const float4* W1e = (const float4*)(W1g + e * WID * WID);
        for (int i = t2; i < 64 * 16; i += 128) {
            int k = i >> 4, cq = i & 15;
            float4 v = W1e[k * 16 + cq];
            u32 h01, h23; split4h(v, h01, h23);
            u32 off = SWZ((u32)(k * 128 + cq * 8));
            *(u32*)(sm + SM_W1H + off) = h01; *(u32*)(sm + SM_W1H + off + 4) = h23;
        }
        const float4* W2e = (const float4*)(W2g + e * WID * DOUT);
        for (int i = t2; i < 64 * 8; i += 128) {
            int k = i >> 3, cq = i & 7;
            float4 v = W2e[k * 8 + cq];
            u32 h01, h23; split4h(v, h01, h23);
            u32 off = SWZ((u32)(k * 128 + cq * 8));
            *(u32*)(sm + SM_W2H + off) = h01; *(u32*)(sm + SM_W2H + off + 4) = h23;
        }
        if (t2 < WID) { B0s[t2] = b0g[e * WID + t2]; B1s[t2] = b1g[e * WID + t2]; }
        if (t2 >= WID && t2 < WID + DOUT) B2s[t2 - WID] = b2g[e * DOUT + t2 - WID];
    }
    __syncthreads();

    // fragment lane coordinates (warp grid: 4 M-groups x 2 N-groups)
    const int wm = wid >> 1, wn = wid & 1;
    const int amat = lane >> 3, amr = lane & 7;
    const int arow_off = ((amat & 1) << 3) + amr;
    const int akoff = amat >> 1;
    // x4-trans B lane coords: matrix idx = lane>>3; k-half = midx&1, n-half = midx>>1
    const int bk = ((lane >> 3) & 1) * 8 + (lane & 7);
    const int bnh = (lane >> 4) * 8;

    float C[2][4][4];

    // ================= LAYER 0 (K=80, N=64) =================
#pragma unroll
    for (int mt = 0; mt < 2; mt++)
#pragma unroll
        for (int nt = 0; nt < 4; nt++)
#pragma unroll
            for (int q = 0; q < 4; q++) C[mt][nt][q] = 0.0f;

#pragma unroll
    for (int mt = 0; mt < 2; mt++) {
        int arow = wm * 32 + mt * 16 + arow_off;
        u32 arb = (u32)(arow * 128);
        int ar7 = arow & 7;
        u32 ah[5][4], al[5][4];
#pragma unroll
        for (int kt = 0; kt < 4; kt++) {
            u32 off = arb + (u32)(((2 * kt + akoff) ^ ar7) << 4);
            ldmA(ah[kt], smb + SM_XH0 + off);
            ldmA(al[kt], smb + SM_XL0 + off);
        }
        {
            u32 off = (u32)(arow * 48 + (akoff << 4));
            ldmA(ah[4], smb + SM_XH1 + off);
            ldmA(al[4], smb + SM_XL1 + off);
        }
#pragma unroll
        for (int np = 0; np < 2; np++) {
            int n0 = wn * 32 + np * 16 + bnh;
#pragma unroll
            for (int kt = 0; kt < 5; kt++) {
                u32 bh[4];
                if (kt < 4) {
                    u32 off = SWZ((u32)((16 * kt + bk) * 128 + n0 * 2));
                    ldmBT4(bh, smb + SM_W0H + off);
                } else {
                    u32 off = SWZ((u32)(bk * 128 + n0 * 2));   // tail panel rows 0..15
                    ldmBT4(bh, smb + SM_W0HT + off);
                }
#pragma unroll
                for (int sub = 0; sub < 2; sub++) {
                    float* c = C[mt][2 * np + sub];
                    mma16816(c, ah[kt], &bh[2 * sub]);
                    mma16816(c, al[kt], &bh[2 * sub]);
                }
            }
        }
    }
    __syncthreads();   // all warps done reading X before H overwrites panel0

    // epilogue L0: bias+relu, split, write H into XH0/XL0
#pragma unroll
    for (int mt = 0; mt < 2; mt++)
#pragma unroll
        for (int nt = 0; nt < 4; nt++) {
            int row0 = wm * 32 + mt * 16 + (lane >> 2);
            int j0 = wn * 32 + nt * 8 + (lane & 3) * 2;
            float v0 = fmaxf(C[mt][nt][0] + B0s[j0], 0.0f);
            float v1 = fmaxf(C[mt][nt][1] + B0s[j0 + 1], 0.0f);
            float v2 = fmaxf(C[mt][nt][2] + B0s[j0], 0.0f);
            float v3 = fmaxf(C[mt][nt][3] + B0s[j0 + 1], 0.0f);
            u32 oa = SWZ((u32)(row0 * 128 + j0 * 2));
            u32 ob = SWZ((u32)((row0 + 8) * 128 + j0 * 2));
            store_split(sm, SM_XH0 + oa, SM_XL0 + oa, v0, v1);
            store_split(sm, SM_XH0 + ob, SM_XL0 + ob, v2, v3);
        }
    __syncthreads();

    // ================= LAYER 1 (K=64, N=64) =================
#pragma unroll
    for (int mt = 0; mt < 2; mt++)
#pragma unroll
        for (int nt = 0; nt < 4; nt++)
#pragma unroll
            for (int q = 0; q < 4; q++) C[mt][nt][q] = 0.0f;

#pragma unroll
    for (int mt = 0; mt < 2; mt++) {
        int arow = wm * 32 + mt * 16 + arow_off;
        u32 arb = (u32)(arow * 128);
        int ar7 = arow & 7;
        u32 ah[4][4], al[4][4];
#pragma unroll
        for (int kt = 0; kt < 4; kt++) {
            u32 off = arb + (u32)(((2 * kt + akoff) ^ ar7) << 4);
            ldmA(ah[kt], smb + SM_XH0 + off);
            ldmA(al[kt], smb + SM_XL0 + off);
        }
#pragma unroll
        for (int np = 0; np < 2; np++) {
            int n0 = wn * 32 + np * 16 + bnh;
#pragma unroll
            for (int kt = 0; kt < 4; kt++) {
                u32 bh[4];
                u32 off = SWZ((u32)((16 * kt + bk) * 128 + n0 * 2));
                ldmBT4(bh, smb + SM_W1H + off);
#pragma unroll
                for (int sub = 0; sub < 2; sub++) {
                    float* c = C[mt][2 * np + sub];
                    mma16816(c, ah[kt], &bh[2 * sub]);
                    mma16816(c, al[kt], &bh[2 * sub]);
                }
            }
        }
    }
    __syncthreads();   // done reading H before G overwrites the same panels

    // epilogue L1: bias+relu, split, write G into XH0/XL0
#pragma unroll
    for (int mt = 0; mt < 2; mt++)
#pragma unroll
        for (int nt = 0; nt < 4; nt++) {
            int row0 = wm * 32 + mt * 16 + (lane >> 2);
            int j0 = wn * 32 + nt * 8 + (lane & 3) * 2;
            float v0 = fmaxf(C[mt][nt][0] + B1s[j0], 0.0f);
            float v1 = fmaxf(C[mt][nt][1] + B1s[j0 + 1], 0.0f);
            float v2 = fmaxf(C[mt][nt][2] + B1s[j0], 0.0f);
            float v3 = fmaxf(C[mt][nt][3] + B1s[j0 + 1], 0.0f);
            u32 oa = SWZ((u32)(row0 * 128 + j0 * 2));
            u32 ob = SWZ((u32)((row0 + 8) * 128 + j0 * 2));
            store_split(sm, SM_XH0 + oa, SM_XL0 + oa, v0, v1);
            store_split(sm, SM_XH0 + ob, SM_XL0 + ob, v2, v3);
        }
    __syncthreads();

    // ================= LAYER 2 (K=64, N=32) =================
#pragma unroll
    for (int mt = 0; mt < 2; mt++)
#pragma unroll
        for (int nt = 0; nt < 2; nt++)
#pragma unroll
            for (int q = 0; q < 4; q++) C[mt][nt][q] = 0.0f;

#pragma unroll
    for (int mt = 0; mt < 2; mt++) {
        int arow = wm * 32 + mt * 16 + arow_off;
        u32 arb = (u32)(arow * 128);
        int ar7 = arow & 7;
        u32 ah[4][4], al[4][4];
#pragma unroll
        for (int kt = 0; kt < 4; kt++) {
            u32 off = arb + (u32)(((2 * kt + akoff) ^ ar7) << 4);
            ldmA(ah[kt], smb + SM_XH0 + off);
            ldmA(al[kt], smb + SM_XL0 + off);
        }
        {
            int n0 = wn * 16 + bnh;
#pragma unroll
            for (int kt = 0; kt < 4; kt++) {
                u32 bh[4];
                u32 off = SWZ((u32)((16 * kt + bk) * 128 + n0 * 2));
                ldmBT4(bh, smb + SM_W2H + off);
#pragma unroll
                for (int sub = 0; sub < 2; sub++) {
                    float* c = C[mt][sub];
                    mma16816(c, ah[kt], &bh[2 * sub]);
                    mma16816(c, al[kt], &bh[2 * sub]);
                }
            }
        }
    }

    // final epilogue: bias + shuffle-coalesced float4 scatter
#pragma unroll
    for (int mt = 0; mt < 2; mt++)
#pragma unroll
        for (int nt = 0; nt < 2; nt++) {
            int row0 = wm * 32 + mt * 16 + (lane >> 2);
            int q = lane & 3;
            int j0 = wn * 16 + nt * 8 + 2 * q;
            float a0 = C[mt][nt][0] + B2s[j0];
            float a1 = C[mt][nt][1] + B2s[j0 + 1];
            float b0 = C[mt][nt][2] + B2s[j0];
            float b1 = C[mt][nt][3] + B2s[j0 + 1];
            float pa0 = __shfl_xor_sync(0xFFFFFFFFu, a0, 1);
            float pa1 = __shfl_xor_sync(0xFFFFFFFFu, a1, 1);
            float pb0 = __shfl_xor_sync(0xFFFFFFFFu, b0, 1);
            float pb1 = __shfl_xor_sync(0xFFFFFFFFu, b1, 1);
            if (!(q & 1)) {
                int colb = wn * 16 + nt * 8 + 2 * q;
                if (row0 < cnt)
                    *(float4*)(out + (size_t)sids[row0] * DOUT + colb) =
                        make_float4(a0, a1, pa0, pa1);
                if (row0 + 8 < cnt)
                    *(float4*)(out + (size_t)sids[row0 + 8] * DOUT + colb) =
                        make_float4(b0, b1, pb0, pb1);
            }
        }
}

// ---------------- launch ----------------
extern "C" void kernel_launch(void* const* d_in, const int* in_sizes, int n_in,
                              void* d_out, int out_size) {
    (void)in_sizes; (void)n_in; (void)out_size;
    const int*   idxs      = (const int*)d_in[0];
    const float* positions = (const float*)d_in[1];
    const float* viewdirs  = (const float*)d_in[2];
    const float* features  = (const float*)d_in[3];
    const float* W0 = (const float*)d_in[4];
    const float* b0 = (const float*)d_in[5];
    const float* W1 = (const float*)d_in[6];
    const float* b1 = (const float*)d_in[7];
    const float* W2 = (const float*)d_in[8];
    const float* b2 = (const float*)d_in[9];
    float* out = (float*)d_out;

    cudaFuncSetAttribute(k_mlp, cudaFuncAttributeMaxDynamicSharedMemorySize, SMEM_BYTES);

    k_hist<<<NSCAT, 256>>>(idxs);
    k_scan<<<1, 1>>>();
    k_scatter<<<NSCAT, 256>>>(idxs);
    k_mlp<<<MAXTILES, NT, SMEM_BYTES>>>(positions, viewdirs, features,
                                        W0, b0, W1, b1, W2, b2, out);
}

// round 11
// speedup vs baseline: 1.3743x; 1.0585x over previous
#include <cuda_runtime.h>
#include <cuda_fp16.h>

typedef unsigned int u32;

// ---------------- problem constants ----------------
#define NS    65536
#define KEXP  8
#define DIN   74
#define WID   64
#define DOUT  32
#define TILE  128
#define NT    256
#define MAXTILES (NS / TILE + KEXP)
#define NSCAT 256

// packed per-expert weight image (matches smem panel layout exactly)
// [0:8192)      W0H  [64 k][128B] swizzled
// [8192:10240)  W0HT [16 k][128B]
// [10240:18432) W1H  [64 k][128B]
// [18432:26624) W2H  [64 k][128B] (32 n -> 64B used)
// [26624:27264) biases fp32: B0[64] B1[64] B2[32]
#define WPACK_BYTES 27264

// ---------------- smem layout (bytes) ----------------
#define SM_XH0  0                  // X/H/G hi: [128 rows][128B] (k 0..63)
#define SM_XL0  16384              // X/H/G lo
#define SM_XH1  32768              // X hi tail: [128 rows][48B] (k 64..79)
#define SM_XL1  38912
#define SM_W0H  45056              // weight image copied here (27264 B)
#define SM_W0HT (SM_W0H + 8192)
#define SM_W1H  (SM_W0H + 10240)
#define SM_W2H  (SM_W0H + 18432)
#define SM_B0   (SM_W0H + 26624)
#define SM_B1   (SM_B0 + 256)
#define SM_B2   (SM_B1 + 256)
#define SM_SIDS 72320
#define SMEM_BYTES (SM_SIDS + TILE * 4)   // 72832 -> 3 CTAs/SM

#define SWZ(off) ((off) ^ (((off) >> 3) & 0x70))

// ---------------- device scratch ----------------
__device__ int g_hist[KEXP];
__device__ int g_offs[KEXP + 1];
__device__ int g_cursor[KEXP];
__device__ int g_order[NS];
__device__ __align__(16) char g_wpack[KEXP][WPACK_BYTES];

// ---------------- bucketing ----------------
__global__ void k_hist(const int* __restrict__ idxs) {
    __shared__ int sh[KEXP];
    if (threadIdx.x < KEXP) sh[threadIdx.x] = 0;
    __syncthreads();
    atomicAdd(&sh[idxs[blockIdx.x * 256 + threadIdx.x]], 1);
    __syncthreads();
    if (threadIdx.x < KEXP) atomicAdd(&g_hist[threadIdx.x], sh[threadIdx.x]);
}
__global__ void k_scan() {
    int acc = 0;
    for (int e = 0; e < KEXP; e++) {
        g_offs[e] = acc; g_cursor[e] = acc;
        acc += g_hist[e];
        g_hist[e] = 0;
    }
    g_offs[KEXP] = acc;
}
__global__ void k_scatter(const int* __restrict__ idxs) {
    __shared__ int s_loc[KEXP];
    __shared__ int s_base[KEXP];
    if (threadIdx.x < KEXP) s_loc[threadIdx.x] = 0;
    __syncthreads();
    int i = blockIdx.x * 256 + threadIdx.x;
    int e = idxs[i];
    int r = atomicAdd(&s_loc[e], 1);
    __syncthreads();
    if (threadIdx.x < KEXP)
        s_base[threadIdx.x] = atomicAdd(&g_cursor[threadIdx.x], s_loc[threadIdx.x]);
    __syncthreads();
    g_order[s_base[e] + r] = i;
}

// ---------------- helpers ----------------
__device__ __forceinline__ u32 smem_u32(const void* p) {
    u32 a; asm("{ .reg .u64 t; cvta.to.shared.u64 t, %1; cvt.u32.u64 %0, t; }" : "=r"(a) : "l"(p));
    return a;
}
__device__ __forceinline__ void ldmA(u32 a[4], u32 addr) {
    asm volatile("ldmatrix.sync.aligned.m8n8.x4.shared.b16 {%0,%1,%2,%3}, [%4];"
                 : "=r"(a[0]), "=r"(a[1]), "=r"(a[2]), "=r"(a[3]) : "r"(addr));
}
__device__ __forceinline__ void ldmBT4(u32 b[4], u32 addr) {
    asm volatile("ldmatrix.sync.aligned.m8n8.x4.trans.shared.b16 {%0,%1,%2,%3}, [%4];"
                 : "=r"(b[0]), "=r"(b[1]), "=r"(b[2]), "=r"(b[3]) : "r"(addr));
}
__device__ __forceinline__ void mma16816(float c[4], const u32 a[4], const u32 b[2]) {
    asm volatile(
        "mma.sync.aligned.m16n8k16.row.col.f32.f16.f16.f32 "
        "{%0,%1,%2,%3}, {%4,%5,%6,%7}, {%8,%9}, {%0,%1,%2,%3};"
        : "+f"(c[0]), "+f"(c[1]), "+f"(c[2]), "+f"(c[3])
        : "r"(a[0]), "r"(a[1]), "r"(a[2]), "r"(a[3]), "r"(b[0]), "r"(b[1]));
}
__device__ __forceinline__ u32 hpack(__half a, __half b) {
    __half2 t(a, b);
    return *reinterpret_cast<u32*>(&t);
}
__device__ __forceinline__ void store_split(char* sm, u32 offH, u32 offL, float v0, float v1) {
    __half h0 = __float2half_rn(v0), h1 = __float2half_rn(v1);
    float l0 = v0 - __half2float(h0), l1 = v1 - __half2float(h1);
    *(u32*)(sm + offH) = hpack(h0, h1);
    *(u32*)(sm + offL) = hpack(__float2half_rn(l0), __float2half_rn(l1));
}
__device__ __forceinline__ void split4h(float4 v, u32& h01, u32& h23) {
    h01 = hpack(__float2half_rn(v.x), __float2half_rn(v.y));
    h23 = hpack(__float2half_rn(v.z), __float2half_rn(v.w));
}
__device__ __forceinline__ void cp16(u32 dst_smem, const void* src) {
    asm volatile("cp.async.ca.shared.global [%0], [%1], 16;" :: "r"(dst_smem), "l"(src) : "memory");
}

// ---------------- weight pre-pack kernel (once per launch) ----------------
// 64 blocks: expert e = bid>>3, slice = bid&7 (2048 virtual threads per expert)
__global__ void k_prep(const float* __restrict__ W0g, const float* __restrict__ b0g,
                       const float* __restrict__ W1g, const float* __restrict__ b1g,
                       const float* __restrict__ W2g, const float* __restrict__ b2g) {
    int e = blockIdx.x >> 3;
    int vt = (blockIdx.x & 7) * 256 + threadIdx.x;   // 0..2047
    char* dst = g_wpack[e];

    const float4* W0e = (const float4*)(W0g + e * DIN * WID);
    for (int i = vt; i < 80 * 16; i += 2048) {
        int k = i >> 4, cq = i & 15;
        float4 v = (k < DIN) ? W0e[k * 16 + cq] : make_float4(0.f, 0.f, 0.f, 0.f);
        u32 h01, h23; split4h(v, h01, h23);
        u32 base = 0;
        if (k >= 64) { base = 8192; k -= 64; }
        u32 off = base + SWZ((u32)(k * 128 + cq * 8));
        *(u32*)(dst + off) = h01; *(u32*)(dst + off + 4) = h23;
    }
    const float4* W1e = (const float4*)(W1g + e * WID * WID);
    for (int i = vt; i < 64 * 16; i += 2048) {
        int k = i >> 4, cq = i & 15;
        float4 v = W1e[k * 16 + cq];
        u32 h01, h23; split4h(v, h01, h23);
        u32 off = 10240 + SWZ((u32)(k * 128 + cq * 8));
        *(u32*)(dst + off) = h01; *(u32*)(dst + off + 4) = h23;
    }
    const float4* W2e = (const float4*)(W2g + e * WID * DOUT);
    for (int i = vt; i < 64 * 8; i += 2048) {
        int k = i >> 3, cq = i & 7;
        float4 v = W2e[k * 8 + cq];
        u32 h01, h23; split4h(v, h01, h23);
        u32 off = 18432 + SWZ((u32)(k * 128 + cq * 8));
        *(u32*)(dst + off) = h01; *(u32*)(dst + off + 4) = h23;
    }
    float* bd = (float*)(dst + 26624);
    for (int i = vt; i < 160; i += 2048)
        bd[i] = (i < 64) ? b0g[e * WID + i]
              : (i < 128) ? b1g[e * WID + i - 64]
              : b2g[e * DOUT + i - 128];
}

// ---------------- fused MMA MLP kernel ----------------
__global__ void __launch_bounds__(NT, 3) k_mlp(
    const float* __restrict__ positions, const float* __restrict__ viewdirs,
    const float* __restrict__ features,
    float* __restrict__ out) {
    extern __shared__ char sm[];
    const u32 smb = smem_u32(sm);
    const int tid = threadIdx.x, lane = tid & 31, wid = tid >> 5;

    // blockIdx -> (expert, local tile)
    int e = -1, lt = 0;
    {
        int b = blockIdx.x, acc = 0;
#pragma unroll
        for (int i = 0; i < KEXP; i++) {
            int tiles = (g_offs[i + 1] - g_offs[i] + TILE - 1) / TILE;
            if (e < 0 && b < acc + tiles) { e = i; lt = b - acc; }
            acc += tiles;
        }
    }
    if (e < 0) return;
    const int base = g_offs[e] + lt * TILE;
    const int cnt = min(TILE, g_offs[e + 1] - base);

    int* sids = (int*)(sm + SM_SIDS);
    float* B0s = (float*)(sm + SM_B0);
    float* B1s = (float*)(sm + SM_B1);
    float* B2s = (float*)(sm + SM_B2);

    // ================= STAGING =================
    if (tid < TILE) {
        int n = g_order[base + min(tid, cnt - 1)];   // pad partial tiles with a valid row
        sids[tid] = n;
        float x[80];
        const float4* f4 = (const float4*)(features + (size_t)n * 32);
#pragma unroll
        for (int i = 0; i < 8; i++) {
            float4 f = f4[i];
            x[4 * i] = f.x; x[4 * i + 1] = f.y; x[4 * i + 2] = f.z; x[4 * i + 3] = f.w;
        }
        float p0 = positions[n * 3], p1 = positions[n * 3 + 1], p2 = positions[n * 3 + 2];
        x[32] = p0; x[33] = p1; x[34] = p2;
#pragma unroll
        for (int s = 0; s < 2; s++) {
            float sc = (float)(1 << s);
            x[35 + 3 * s] = __sinf(p0 * sc); x[36 + 3 * s] = __sinf(p1 * sc); x[37 + 3 * s] = __sinf(p2 * sc);
            x[41 + 3 * s] = __cosf(p0 * sc); x[42 + 3 * s] = __cosf(p1 * sc); x[43 + 3 * s] = __cosf(p2 * sc);
        }
        float q0 = viewdirs[n * 3], q1 = viewdirs[n * 3 + 1], q2 = viewdirs[n * 3 + 2];
        x[47] = q0; x[48] = q1; x[49] = q2;
#pragma unroll
        for (int s = 0; s < 4; s++) {
            float sc = (float)(1 << s);
            x[50 + 3 * s] = __sinf(q0 * sc); x[51 + 3 * s] = __sinf(q1 * sc); x[52 + 3 * s] = __sinf(q2 * sc);
            x[62 + 3 * s] = __cosf(q0 * sc); x[63 + 3 * s] = __cosf(q1 * sc); x[64 + 3 * s] = __cosf(q2 * sc);
        }
#pragma unroll
        for (int k = DIN; k < 80; k++) x[k] = 0.0f;
#pragma unroll
        for (int j = 0; j < 40; j++) {
            if (j < 32) {
                u32 off = SWZ((u32)(tid * 128 + j * 4));
                store_split(sm, SM_XH0 + off, SM_XL0 + off, x[2 * j], x[2 * j + 1]);
            } else {
                u32 off = (u32)(tid * 48 + (j - 32) * 4);
                store_split(sm, SM_XH1 + off, SM_XL1 + off, x[2 * j], x[2 * j + 1]);
            }
        }
    } else {
        // bulk-copy pre-packed weight image (27264 B) via cp.async
        int t2 = tid - TILE;   // 0..127
        const char* src = g_wpack[e];
#pragma unroll
        for (int i = t2 * 16; i < WPACK_BYTES; i += 128 * 16)
            cp16(smb + SM_W0H + i, src + i);
        asm volatile("cp.async.commit_group;" ::: "memory");
        asm volatile("cp.async.wait_group 0;" ::: "memory");
    }
    __syncthreads();

    // fragment lane coordinates (warp grid: 4 M-groups x 2 N-groups)
    const int wm = wid >> 1, wn = wid & 1;
    const int amat = lane >> 3, amr = lane & 7;
    const int arow_off = ((amat & 1) << 3) + amr;
    const int akoff = amat >> 1;
    // x4-trans B lane coords: k = 16kt + 8*((lane>>3)&1) + (lane&7); n-half = (lane>>4)*8
    const int bk = ((lane >> 3) & 1) * 8 + (lane & 7);
    const int bnh = (lane >> 4) * 8;
    const u32 bswz = ((u32)(bk & 7)) << 4;   // SWZ xor term, constant per thread
    const u32 brow = (u32)(bk * 128);

    float C[2][4][4];

    // ================= LAYER 0 (K=80, N=64) =================
#pragma unroll
    for (int mt = 0; mt < 2; mt++)
#pragma unroll
        for (int nt = 0; nt < 4; nt++)
#pragma unroll
            for (int q = 0; q < 4; q++) C[mt][nt][q] = 0.0f;

#pragma unroll
    for (int mt = 0; mt < 2; mt++) {
        int arow = wm * 32 + mt * 16 + arow_off;
        u32 arb = (u32)(arow * 128);
        int ar7 = arow & 7;
        u32 ah[5][4], al[5][4];
#pragma unroll
        for (int kt = 0; kt < 4; kt++) {
            u32 off = arb + (u32)(((2 * kt + akoff) ^ ar7) << 4);
            ldmA(ah[kt], smb + SM_XH0 + off);
            ldmA(al[kt], smb + SM_XL0 + off);
        }
        {
            u32 off = (u32)(arow * 48 + (akoff << 4));
            ldmA(ah[4], smb + SM_XH1 + off);
            ldmA(al[4], smb + SM_XL1 + off);
        }
#pragma unroll
        for (int np = 0; np < 2; np++) {
            u32 bcol = ((u32)((wn * 32 + np * 16 + bnh) * 2)) ^ bswz;
            u32 bb = smb + SM_W0H + brow + bcol;
#pragma unroll
            for (int kt = 0; kt < 5; kt++) {
                u32 bh[4];
                if (kt < 4) ldmBT4(bh, bb + kt * 2048);
                else        ldmBT4(bh, smb + SM_W0HT + brow + bcol);
#pragma unroll
                for (int sub = 0; sub < 2; sub++) {
                    float* c = C[mt][2 * np + sub];
                    mma16816(c, ah[kt], &bh[2 * sub]);
                    mma16816(c, al[kt], &bh[2 * sub]);
                }
            }
        }
    }
    __syncthreads();   // all warps done reading X before H overwrites panel0

    // epilogue L0: bias+relu, split, write H into XH0/XL0
#pragma unroll
    for (int mt = 0; mt < 2; mt++)
#pragma unroll
        for (int nt = 0; nt < 4; nt++) {
            int row0 = wm * 32 + mt * 16 + (lane >> 2);
            int j0 = wn * 32 + nt * 8 + (lane & 3) * 2;
            float v0 = fmaxf(C[mt][nt][0] + B0s[j0], 0.0f);
            float v1 = fmaxf(C[mt][nt][1] + B0s[j0 + 1], 0.0f);
            float v2 = fmaxf(C[mt][nt][2] + B0s[j0], 0.0f);
            float v3 = fmaxf(C[mt][nt][3] + B0s[j0 + 1], 0.0f);
            u32 oa = SWZ((u32)(row0 * 128 + j0 * 2));
            u32 ob = SWZ((u32)((row0 + 8) * 128 + j0 * 2));
            store_split(sm, SM_XH0 + oa, SM_XL0 + oa, v0, v1);
            store_split(sm, SM_XH0 + ob, SM_XL0 + ob, v2, v3);
        }
    __syncthreads();

    // ================= LAYER 1 (K=64, N=64) =================
#pragma unroll
    for (int mt = 0; mt < 2; mt++)
#pragma unroll
        for (int nt = 0; nt < 4; nt++)
#pragma unroll
            for (int q = 0; q < 4; q++) C[mt][nt][q] = 0.0f;

#pragma unroll
    for (int mt = 0; mt < 2; mt++) {
        int arow = wm * 32 + mt * 16 + arow_off;
        u32 arb = (u32)(arow * 128);
        int ar7 = arow & 7;
        u32 ah[4][4], al[4][4];
#pragma unroll
        for (int kt = 0; kt < 4; kt++) {
            u32 off = arb + (u32)(((2 * kt + akoff) ^ ar7) << 4);
            ldmA(ah[kt], smb + SM_XH0 + off);
            ldmA(al[kt], smb + SM_XL0 + off);
        }
#pragma unroll
        for (int np = 0; np < 2; np++) {
            u32 bcol = ((u32)((wn * 32 + np * 16 + bnh) * 2)) ^ bswz;
            u32 bb = smb + SM_W1H + brow + bcol;
#pragma unroll
            for (int kt = 0; kt < 4; kt++) {
                u32 bh[4];
                ldmBT4(bh, bb + kt * 2048);
#pragma unroll
                for (int sub = 0; sub < 2; sub++) {
                    float* c = C[mt][2 * np + sub];
                    mma16816(c, ah[kt], &bh[2 * sub]);
                    mma16816(c, al[kt], &bh[2 * sub]);
                }
            }
        }
    }
    __syncthreads();   // done reading H before G overwrites the same panels

    // epilogue L1: bias+relu, split, write G into XH0/XL0
#pragma unroll
    for (int mt = 0; mt < 2; mt++)
#pragma unroll
        for (int nt = 0; nt < 4; nt++) {
            int row0 = wm * 32 + mt * 16 + (lane >> 2);
            int j0 = wn * 32 + nt * 8 + (lane & 3) * 2;
            float v0 = fmaxf(C[mt][nt][0] + B1s[j0], 0.0f);
            float v1 = fmaxf(C[mt][nt][1] + B1s[j0 + 1], 0.0f);
            float v2 = fmaxf(C[mt][nt][2] + B1s[j0], 0.0f);
            float v3 = fmaxf(C[mt][nt][3] + B1s[j0 + 1], 0.0f);
            u32 oa = SWZ((u32)(row0 * 128 + j0 * 2));
            u32 ob = SWZ((u32)((row0 + 8) * 128 + j0 * 2));
            store_split(sm, SM_XH0 + oa, SM_XL0 + oa, v0, v1);
            store_split(sm, SM_XH0 + ob, SM_XL0 + ob, v2, v3);
        }
    __syncthreads();

    // ================= LAYER 2 (K=64, N=32) =================
#pragma unroll
    for (int mt = 0; mt < 2; mt++)
#pragma unroll
        for (int nt = 0; nt < 2; nt++)
#pragma unroll
            for (int q = 0; q < 4; q++) C[mt][nt][q] = 0.0f;

#pragma unroll
    for (int mt = 0; mt < 2; mt++) {
        int arow = wm * 32 + mt * 16 + arow_off;
        u32 arb = (u32)(arow * 128);
        int ar7 = arow & 7;
        u32 ah[4][4], al[4][4];
#pragma unroll
        for (int kt = 0; kt < 4; kt++) {
            u32 off = arb + (u32)(((2 * kt + akoff) ^ ar7) << 4);
            ldmA(ah[kt], smb + SM_XH0 + off);
            ldmA(al[kt], smb + SM_XL0 + off);
        }
        {
            u32 bcol = ((u32)((wn * 16 + bnh) * 2)) ^ bswz;
            u32 bb = smb + SM_W2H + brow + bcol;
#pragma unroll
            for (int kt = 0; kt < 4; kt++) {
                u32 bh[4];
                ldmBT4(bh, bb + kt * 2048);
#pragma unroll
                for (int sub = 0; sub < 2; sub++) {
                    float* c = C[mt][sub];
                    mma16816(c, ah[kt], &bh[2 * sub]);
                    mma16816(c, al[kt], &bh[2 * sub]);
                }
            }
        }
    }

    // final epilogue: bias + shuffle-coalesced float4 scatter
#pragma unroll
    for (int mt = 0; mt < 2; mt++)
#pragma unroll
        for (int nt = 0; nt < 2; nt++) {
            int row0 = wm * 32 + mt * 16 + (lane >> 2);
            int q = lane & 3;
            int j0 = wn * 16 + nt * 8 + 2 * q;
            float a0 = C[mt][nt][0] + B2s[j0];
            float a1 = C[mt][nt][1] + B2s[j0 + 1];
            float b0 = C[mt][nt][2] + B2s[j0];
            float b1 = C[mt][nt][3] + B2s[j0 + 1];
            float pa0 = __shfl_xor_sync(0xFFFFFFFFu, a0, 1);
            float pa1 = __shfl_xor_sync(0xFFFFFFFFu, a1, 1);
            float pb0 = __shfl_xor_sync(0xFFFFFFFFu, b0, 1);
            float pb1 = __shfl_xor_sync(0xFFFFFFFFu, b1, 1);
            if (!(q & 1)) {
                int colb = wn * 16 + nt * 8 + 2 * q;
                if (row0 < cnt)
                    *(float4*)(out + (size_t)sids[row0] * DOUT + colb) =
                        make_float4(a0, a1, pa0, pa1);
                if (row0 + 8 < cnt)
                    *(float4*)(out + (size_t)sids[row0 + 8] * DOUT + colb) =
                        make_float4(b0, b1, pb0, pb1);
            }
        }
}

// ---------------- launch ----------------
extern "C" void kernel_launch(void* const* d_in, const int* in_sizes, int n_in,
                              void* d_out, int out_size) {
    (void)in_sizes; (void)n_in; (void)out_size;
    const int*   idxs      = (const int*)d_in[0];
    const float* positions = (const float*)d_in[1];
    const float* viewdirs  = (const float*)d_in[2];
    const float* features  = (const float*)d_in[3];
    const float* W0 = (const float*)d_in[4];
    const float* b0 = (const float*)d_in[5];
    const float* W1 = (const float*)d_in[6];
    const float* b1 = (const float*)d_in[7];
    const float* W2 = (const float*)d_in[8];
    const float* b2 = (const float*)d_in[9];
    float* out = (float*)d_out;

    cudaFuncSetAttribute(k_mlp, cudaFuncAttributeMaxDynamicSharedMemorySize, SMEM_BYTES);

    k_prep<<<64, 256>>>(W0, b0, W1, b1, W2, b2);
    k_hist<<<NSCAT, 256>>>(idxs);
    k_scan<<<1, 1>>>();
    k_scatter<<<NSCAT, 256>>>(idxs);
    k_mlp<<<MAXTILES, NT, SMEM_BYTES>>>(positions, viewdirs, features, out);
}

// round 12
// speedup vs baseline: 1.6108x; 1.1721x over previous
#include <cuda_runtime.h>
#include <cuda_fp16.h>

typedef unsigned int u32;

// ---------------- problem constants ----------------
#define NS    65536
#define KEXP  8
#define DIN   74
#define WID   64
#define DOUT  32
#define TILE  128
#define NT    256
#define MAXTILES (NS / TILE + KEXP)
#define NHB   256                  // hist/scatter blocks (256 samples each)

// packed per-expert weight image (matches smem panel layout exactly)
#define WPACK_BYTES 27264

// ---------------- smem layout (bytes) ----------------
#define SM_XH0  0                  // X/H/G hi: [128 rows][128B] (k 0..63)
#define SM_XL0  16384              // X/H/G lo
#define SM_XH1  32768              // X hi tail: [128 rows][48B] (k 64..79)
#define SM_XL1  38912
#define SM_W0H  45056              // weight image copied here (27264 B)
#define SM_W0HT (SM_W0H + 8192)
#define SM_W1H  (SM_W0H + 10240)
#define SM_W2H  (SM_W0H + 18432)
#define SM_B0   (SM_W0H + 26624)
#define SM_B1   (SM_B0 + 256)
#define SM_B2   (SM_B1 + 256)
#define SM_SIDS 72320
#define SMEM_BYTES (SM_SIDS + TILE * 4)   // 72832 -> 3 CTAs/SM

#define SWZ(off) ((off) ^ (((off) >> 3) & 0x70))

// ---------------- device scratch ----------------
__device__ int g_bhist[KEXP * NHB];    // [expert][block]
__device__ int g_bbase[KEXP * NHB];    // [expert][block] scatter bases
__device__ int g_offs[KEXP + 1];
__device__ int g_order[NS];
__device__ __align__(16) char g_wpack[KEXP][WPACK_BYTES];

// ---------------- helpers ----------------
__device__ __forceinline__ u32 smem_u32(const void* p) {
    u32 a; asm("{ .reg .u64 t; cvta.to.shared.u64 t, %1; cvt.u32.u64 %0, t; }" : "=r"(a) : "l"(p));
    return a;
}
__device__ __forceinline__ void ldmA(u32 a[4], u32 addr) {
    asm volatile("ldmatrix.sync.aligned.m8n8.x4.shared.b16 {%0,%1,%2,%3}, [%4];"
                 : "=r"(a[0]), "=r"(a[1]), "=r"(a[2]), "=r"(a[3]) : "r"(addr));
}
__device__ __forceinline__ void ldmBT4(u32 b[4], u32 addr) {
    asm volatile("ldmatrix.sync.aligned.m8n8.x4.trans.shared.b16 {%0,%1,%2,%3}, [%4];"
                 : "=r"(b[0]), "=r"(b[1]), "=r"(b[2]), "=r"(b[3]) : "r"(addr));
}
__device__ __forceinline__ void mma16816(float c[4], const u32 a[4], const u32 b[2]) {
    asm volatile(
        "mma.sync.aligned.m16n8k16.row.col.f32.f16.f16.f32 "
        "{%0,%1,%2,%3}, {%4,%5,%6,%7}, {%8,%9}, {%0,%1,%2,%3};"
        : "+f"(c[0]), "+f"(c[1]), "+f"(c[2]), "+f"(c[3])
        : "r"(a[0]), "r"(a[1]), "r"(a[2]), "r"(a[3]), "r"(b[0]), "r"(b[1]));
}
__device__ __forceinline__ u32 hpack(__half a, __half b) {
    __half2 t(a, b);
    return *reinterpret_cast<u32*>(&t);
}
__device__ __forceinline__ void store_split(char* sm, u32 offH, u32 offL, float v0, float v1) {
    __half h0 = __float2half_rn(v0), h1 = __float2half_rn(v1);
    float l0 = v0 - __half2float(h0), l1 = v1 - __half2float(h1);
    *(u32*)(sm + offH) = hpack(h0, h1);
    *(u32*)(sm + offL) = hpack(__float2half_rn(l0), __float2half_rn(l1));
}
__device__ __forceinline__ void split4h(float4 v, u32& h01, u32& h23) {
    h01 = hpack(__float2half_rn(v.x), __float2half_rn(v.y));
    h23 = hpack(__float2half_rn(v.z), __float2half_rn(v.w));
}
__device__ __forceinline__ void cp16(u32 dst_smem, const void* src) {
    asm volatile("cp.async.ca.shared.global [%0], [%1], 16;" :: "r"(dst_smem), "l"(src) : "memory");
}

// ---------------- merged hist (blocks 0..255) + weight pre-pack (blocks 256..319) ----------------
__global__ void k_pre(const int* __restrict__ idxs,
                      const float* __restrict__ W0g, const float* __restrict__ b0g,
                      const float* __restrict__ W1g, const float* __restrict__ b1g,
                      const float* __restrict__ W2g, const float* __restrict__ b2g) {
    if (blockIdx.x < NHB) {
        // private block histogram -> g_bhist (NO global atomics)
        __shared__ int sh[KEXP];
        if (threadIdx.x < KEXP) sh[threadIdx.x] = 0;
        __syncthreads();
        atomicAdd(&sh[idxs[blockIdx.x * 256 + threadIdx.x]], 1);
        __syncthreads();
        if (threadIdx.x < KEXP) g_bhist[threadIdx.x * NHB + blockIdx.x] = sh[threadIdx.x];
        return;
    }
    // weight pre-pack: expert e, slice
    int pb = blockIdx.x - NHB;           // 0..63
    int e = pb >> 3;
    int vt = (pb & 7) * 256 + threadIdx.x;   // 0..2047
    char* dst = g_wpack[e];

    const float4* W0e = (const float4*)(W0g + e * DIN * WID);
    for (int i = vt; i < 80 * 16; i += 2048) {
        int k = i >> 4, cq = i & 15;
        float4 v = (k < DIN) ? W0e[k * 16 + cq] : make_float4(0.f, 0.f, 0.f, 0.f);
        u32 h01, h23; split4h(v, h01, h23);
        u32 base = 0;
        if (k >= 64) { base = 8192; k -= 64; }
        u32 off = base + SWZ((u32)(k * 128 + cq * 8));
        *(u32*)(dst + off) = h01; *(u32*)(dst + off + 4) = h23;
    }
    const float4* W1e = (const float4*)(W1g + e * WID * WID);
    for (int i = vt; i < 64 * 16; i += 2048) {
        int k = i >> 4, cq = i & 15;
        float4 v = W1e[k * 16 + cq];
        u32 h01, h23; split4h(v, h01, h23);
        u32 off = 10240 + SWZ((u32)(k * 128 + cq * 8));
        *(u32*)(dst + off) = h01; *(u32*)(dst + off + 4) = h23;
    }
    const float4* W2e = (const float4*)(W2g + e * WID * DOUT);
    for (int i = vt; i < 64 * 8; i += 2048) {
        int k = i >> 3, cq = i & 7;
        float4 v = W2e[k * 8 + cq];
        u32 h01, h23; split4h(v, h01, h23);
        u32 off = 18432 + SWZ((u32)(k * 128 + cq * 8));
        *(u32*)(dst + off) = h01; *(u32*)(dst + off + 4) = h23;
    }
    float* bd = (float*)(dst + 26624);
    for (int i = vt; i < 160; i += 2048)
        bd[i] = (i < 64) ? b0g[e * WID + i]
              : (i < 128) ? b1g[e * WID + i - 64]
              : b2g[e * DOUT + i - 128];
}

// ---------------- scan: 8 warps, warp e scans its expert's 256 block counts ----------------
__global__ void k_scan() {
    __shared__ int tot[KEXP];
    __shared__ int offs[KEXP];
    int w = threadIdx.x >> 5, lane = threadIdx.x & 31;
    int carry = 0;
    int excl[8];
#pragma unroll
    for (int c = 0; c < 8; c++) {
        int v = g_bhist[w * NHB + c * 32 + lane];
        int s = v;
#pragma unroll
        for (int d = 1; d < 32; d <<= 1) {
            int t = __shfl_up_sync(0xFFFFFFFFu, s, d);
            if (lane >= d) s += t;
        }
        excl[c] = carry + s - v;
        carry += __shfl_sync(0xFFFFFFFFu, s, 31);
    }
    if (lane == 0) tot[w] = carry;
    __syncthreads();
    if (threadIdx.x == 0) {
        int a = 0;
        for (int e = 0; e < KEXP; e++) { offs[e] = a; g_offs[e] = a; a += tot[e]; }
        g_offs[KEXP] = a;
    }
    __syncthreads();
    int o = offs[w];
#pragma unroll
    for (int c = 0; c < 8; c++) g_bbase[w * NHB + c * 32 + lane] = o + excl[c];
}

// ---------------- scatter: block-local ranks + precomputed bases (NO global atomics) ----------------
__global__ void k_scatter(const int* __restrict__ idxs) {
    __shared__ int s_loc[KEXP];
    __shared__ int s_base[KEXP];
    if (threadIdx.x < KEXP) {
        s_loc[threadIdx.x] = 0;
        s_base[threadIdx.x] = g_bbase[threadIdx.x * NHB + blockIdx.x];
    }
    __syncthreads();
    int i = blockIdx.x * 256 + threadIdx.x;
    int e = idxs[i];
    int r = atomicAdd(&s_loc[e], 1);
    g_order[s_base[e] + r] = i;
}

// ---------------- fused MMA MLP kernel ----------------
__global__ void __launch_bounds__(NT, 3) k_mlp(
    const float* __restrict__ positions, const float* __restrict__ viewdirs,
    const float* __restrict__ features,
    float* __restrict__ out) {
    extern __shared__ char sm[];
    const u32 smb = smem_u32(sm);
    const int tid = threadIdx.x, lane = tid & 31, wid = tid >> 5;

    // blockIdx -> (expert, local tile)
    int e = -1, lt = 0;
    {
        int b = blockIdx.x, acc = 0;
#pragma unroll
        for (int i = 0; i < KEXP; i++) {
            int tiles = (g_offs[i + 1] - g_offs[i] + TILE - 1) / TILE;
            if (e < 0 && b < acc + tiles) { e = i; lt = b - acc; }
            acc += tiles;
        }
    }
    if (e < 0) return;
    const int base = g_offs[e] + lt * TILE;
    const int cnt = min(TILE, g_offs[e + 1] - base);

    int* sids = (int*)(sm + SM_SIDS);
    float* B0s = (float*)(sm + SM_B0);
    float* B1s = (float*)(sm + SM_B1);
    float* B2s = (float*)(sm + SM_B2);

    // ================= STAGING =================
    if (tid < TILE) {
        int n = g_order[base + min(tid, cnt - 1)];   // pad partial tiles with a valid row
        sids[tid] = n;
        float x[80];
        const float4* f4 = (const float4*)(features + (size_t)n * 32);
#pragma unroll
        for (int i = 0; i < 8; i++) {
            float4 f = f4[i];
            x[4 * i] = f.x; x[4 * i + 1] = f.y; x[4 * i + 2] = f.z; x[4 * i + 3] = f.w;
        }
        float p0 = positions[n * 3], p1 = positions[n * 3 + 1], p2 = positions[n * 3 + 2];
        x[32] = p0; x[33] = p1; x[34] = p2;
#pragma unroll
        for (int s = 0; s < 2; s++) {
            float sc = (float)(1 << s);
            x[35 + 3 * s] = __sinf(p0 * sc); x[36 + 3 * s] = __sinf(p1 * sc); x[37 + 3 * s] = __sinf(p2 * sc);
            x[41 + 3 * s] = __cosf(p0 * sc); x[42 + 3 * s] = __cosf(p1 * sc); x[43 + 3 * s] = __cosf(p2 * sc);
        }
        float q0 = viewdirs[n * 3], q1 = viewdirs[n * 3 + 1], q2 = viewdirs[n * 3 + 2];
        x[47] = q0; x[48] = q1; x[49] = q2;
#pragma unroll
        for (int s = 0; s < 4; s++) {
            float sc = (float)(1 << s);
            x[50 + 3 * s] = __sinf(q0 * sc); x[51 + 3 * s] = __sinf(q1 * sc); x[52 + 3 * s] = __sinf(q2 * sc);
            x[62 + 3 * s] = __cosf(q0 * sc); x[63 + 3 * s] = __cosf(q1 * sc); x[64 + 3 * s] = __cosf(q2 * sc);
        }
#pragma unroll
        for (int k = DIN; k < 80; k++) x[k] = 0.0f;
#pragma unroll
        for (int j = 0; j < 40; j++) {
            if (j < 32) {
                u32 off = SWZ((u32)(tid * 128 + j * 4));
                store_split(sm, SM_XH0 + off, SM_XL0 + off, x[2 * j], x[2 * j + 1]);
            } else {
                u32 off = (u32)(tid * 48 + (j - 32) * 4);
                store_split(sm, SM_XH1 + off, SM_XL1 + off, x[2 * j], x[2 * j + 1]);
            }
        }
    } else {
        // bulk-copy pre-packed weight image (27264 B) via cp.async
        int t2 = tid - TILE;   // 0..127
        const char* src = g_wpack[e];
#pragma unroll
        for (int i = t2 * 16; i < WPACK_BYTES; i += 128 * 16)
            cp16(smb + SM_W0H + i, src + i);
        asm volatile("cp.async.commit_group;" ::: "memory");
        asm volatile("cp.async.wait_group 0;" ::: "memory");
    }
    __syncthreads();

    // fragment lane coordinates (warp grid: 4 M-groups x 2 N-groups)
    const int wm = wid >> 1, wn = wid & 1;
    const int amat = lane >> 3, amr = lane & 7;
    const int arow_off = ((amat & 1) << 3) + amr;
    const int akoff = amat >> 1;
    const int bk = ((lane >> 3) & 1) * 8 + (lane & 7);
    const int bnh = (lane >> 4) * 8;
    const u32 bswz = ((u32)(bk & 7)) << 4;   // SWZ xor term, constant per thread
    const u32 brow = (u32)(bk * 128);

    float C[2][4][4];

    // ================= LAYER 0 (K=80, N=64) =================
#pragma unroll
    for (int mt = 0; mt < 2; mt++)
#pragma unroll
        for (int nt = 0; nt < 4; nt++)
#pragma unroll
            for (int q = 0; q < 4; q++) C[mt][nt][q] = 0.0f;

#pragma unroll
    for (int mt = 0; mt < 2; mt++) {
        int arow = wm * 32 + mt * 16 + arow_off;
        u32 arb = (u32)(arow * 128);
        int ar7 = arow & 7;
        u32 ah[5][4], al[5][4];
#pragma unroll
        for (int kt = 0; kt < 4; kt++) {
            u32 off = arb + (u32)(((2 * kt + akoff) ^ ar7) << 4);
            ldmA(ah[kt], smb + SM_XH0 + off);
            ldmA(al[kt], smb + SM_XL0 + off);
        }
        {
            u32 off = (u32)(arow * 48 + (akoff << 4));
            ldmA(ah[4], smb + SM_XH1 + off);
            ldmA(al[4], smb + SM_XL1 + off);
        }
#pragma unroll
        for (int np = 0; np < 2; np++) {
            u32 bcol = ((u32)((wn * 32 + np * 16 + bnh) * 2)) ^ bswz;
            u32 bb = smb + SM_W0H + brow + bcol;
#pragma unroll
            for (int kt = 0; kt < 5; kt++) {
                u32 bh[4];
                if (kt < 4) ldmBT4(bh, bb + kt * 2048);
                else        ldmBT4(bh, smb + SM_W0HT + brow + bcol);
#pragma unroll
                for (int sub = 0; sub < 2; sub++) {
                    float* c = C[mt][2 * np + sub];
                    mma16816(c, ah[kt], &bh[2 * sub]);
                    mma16816(c, al[kt], &bh[2 * sub]);
                }
            }
        }
    }
    __syncthreads();   // all warps done reading X before H overwrites panel0

    // epilogue L0: bias+relu, split, write H into XH0/XL0
#pragma unroll
    for (int mt = 0; mt < 2; mt++)
#pragma unroll
        for (int nt = 0; nt < 4; nt++) {
            int row0 = wm * 32 + mt * 16 + (lane >> 2);
            int j0 = wn * 32 + nt * 8 + (lane & 3) * 2;
            float v0 = fmaxf(C[mt][nt][0] + B0s[j0], 0.0f);
            float v1 = fmaxf(C[mt][nt][1] + B0s[j0 + 1], 0.0f);
            float v2 = fmaxf(C[mt][nt][2] + B0s[j0], 0.0f);
            float v3 = fmaxf(C[mt][nt][3] + B0s[j0 + 1], 0.0f);
            u32 oa = SWZ((u32)(row0 * 128 + j0 * 2));
            u32 ob = SWZ((u32)((row0 + 8) * 128 + j0 * 2));
            store_split(sm, SM_XH0 + oa, SM_XL0 + oa, v0, v1);
            store_split(sm, SM_XH0 + ob, SM_XL0 + ob, v2, v3);
        }
    __syncthreads();

    // ================= LAYER 1 (K=64, N=64) =================
#pragma unroll
    for (int mt = 0; mt < 2; mt++)
#pragma unroll
        for (int nt = 0; nt < 4; nt++)
#pragma unroll
            for (int q = 0; q < 4; q++) C[mt][nt][q] = 0.0f;

#pragma unroll
    for (int mt = 0; mt < 2; mt++) {
        int arow = wm * 32 + mt * 16 + arow_off;
        u32 arb = (u32)(arow * 128);
        int ar7 = arow & 7;
        u32 ah[4][4], al[4][4];
#pragma unroll
        for (int kt = 0; kt < 4; kt++) {
            u32 off = arb + (u32)(((2 * kt + akoff) ^ ar7) << 4);
            ldmA(ah[kt], smb + SM_XH0 + off);
            ldmA(al[kt], smb + SM_XL0 + off);
        }
#pragma unroll
        for (int np = 0; np < 2; np++) {
            u32 bcol = ((u32)((wn * 32 + np * 16 + bnh) * 2)) ^ bswz;
            u32 bb = smb + SM_W1H + brow + bcol;
#pragma unroll
            for (int kt = 0; kt < 4; kt++) {
                u32 bh[4];
                ldmBT4(bh, bb + kt * 2048);
#pragma unroll
                for (int sub = 0; sub < 2; sub++) {
                    float* c = C[mt][2 * np + sub];
                    mma16816(c, ah[kt], &bh[2 * sub]);
                    mma16816(c, al[kt], &bh[2 * sub]);
                }
            }
        }
    }
    __syncthreads();   // done reading H before G overwrites the same panels

    // epilogue L1: bias+relu, split, write G into XH0/XL0
#pragma unroll
    for (int mt = 0; mt < 2; mt++)
#pragma unroll
        for (int nt = 0; nt < 4; nt++) {
            int row0 = wm * 32 + mt * 16 + (lane >> 2);
            int j0 = wn * 32 + nt * 8 + (lane & 3) * 2;
            float v0 = fmaxf(C[mt][nt][0] + B1s[j0], 0.0f);
            float v1 = fmaxf(C[mt][nt][1] + B1s[j0 + 1], 0.0f);
            float v2 = fmaxf(C[mt][nt][2] + B1s[j0], 0.0f);
            float v3 = fmaxf(C[mt][nt][3] + B1s[j0 + 1], 0.0f);
            u32 oa = SWZ((u32)(row0 * 128 + j0 * 2));
            u32 ob = SWZ((u32)((row0 + 8) * 128 + j0 * 2));
            store_split(sm, SM_XH0 + oa, SM_XL0 + oa, v0, v1);
            store_split(sm, SM_XH0 + ob, SM_XL0 + ob, v2, v3);
        }
    __syncthreads();

    // ================= LAYER 2 (K=64, N=32) =================
#pragma unroll
    for (int mt = 0; mt < 2; mt++)
#pragma unroll
        for (int nt = 0; nt < 2; nt++)
#pragma unroll
            for (int q = 0; q < 4; q++) C[mt][nt][q] = 0.0f;

#pragma unroll
    for (int mt = 0; mt < 2; mt++) {
        int arow = wm * 32 + mt * 16 + arow_off;
        u32 arb = (u32)(arow * 128);
        int ar7 = arow & 7;
        u32 ah[4][4], al[4][4];
#pragma unroll
        for (int kt = 0; kt < 4; kt++) {
            u32 off = arb + (u32)(((2 * kt + akoff) ^ ar7) << 4);
            ldmA(ah[kt], smb + SM_XH0 + off);
            ldmA(al[kt], smb + SM_XL0 + off);
        }
        {
            u32 bcol = ((u32)((wn * 16 + bnh) * 2)) ^ bswz;
            u32 bb = smb + SM_W2H + brow + bcol;
#pragma unroll
            for (int kt = 0; kt < 4; kt++) {
                u32 bh[4];
                ldmBT4(bh, bb + kt * 2048);
#pragma unroll
                for (int sub = 0; sub < 2; sub++) {
                    float* c = C[mt][sub];
                    mma16816(c, ah[kt], &bh[2 * sub]);
                    mma16816(c, al[kt], &bh[2 * sub]);
                }
            }
        }
    }

    // final epilogue: bias + shuffle-coalesced float4 scatter
#pragma unroll
    for (int mt = 0; mt < 2; mt++)
#pragma unroll
        for (int nt = 0; nt < 2; nt++) {
            int row0 = wm * 32 + mt * 16 + (lane >> 2);
            int q = lane & 3;
            int j0 = wn * 16 + nt * 8 + 2 * q;
            float a0 = C[mt][nt][0] + B2s[j0];
            float a1 = C[mt][nt][1] + B2s[j0 + 1];
            float b0 = C[mt][nt][2] + B2s[j0];
            float b1 = C[mt][nt][3] + B2s[j0 + 1];
            float pa0 = __shfl_xor_sync(0xFFFFFFFFu, a0, 1);
            float pa1 = __shfl_xor_sync(0xFFFFFFFFu, a1, 1);
            float pb0 = __shfl_xor_sync(0xFFFFFFFFu, b0, 1);
            float pb1 = __shfl_xor_sync(0xFFFFFFFFu, b1, 1);
            if (!(q & 1)) {
                int colb = wn * 16 + nt * 8 + 2 * q;
                if (row0 < cnt)
                    *(float4*)(out + (size_t)sids[row0] * DOUT + colb) =
                        make_float4(a0, a1, pa0, pa1);
                if (row0 + 8 < cnt)
                    *(float4*)(out + (size_t)sids[row0 + 8] * DOUT + colb) =
                        make_float4(b0, b1, pb0, pb1);
            }
        }
}

// ---------------- launch ----------------
extern "C" void kernel_launch(void* const* d_in, const int* in_sizes, int n_in,
                              void* d_out, int out_size) {
    (void)in_sizes; (void)n_in; (void)out_size;
    const int*   idxs      = (const int*)d_in[0];
    const float* positions = (const float*)d_in[1];
    const float* viewdirs  = (const float*)d_in[2];
    const float* features  = (const float*)d_in[3];
    const float* W0 = (const float*)d_in[4];
    const float* b0 = (const float*)d_in[5];
    const float* W1 = (const float*)d_in[6];
    const float* b1 = (const float*)d_in[7];
    const float* W2 = (const float*)d_in[8];
    const float* b2 = (const float*)d_in[9];
    float* out = (float*)d_out;

    cudaFuncSetAttribute(k_mlp, cudaFuncAttributeMaxDynamicSharedMemorySize, SMEM_BYTES);

    k_pre<<<NHB + 64, 256>>>(idxs, W0, b0, W1, b1, W2, b2);
    k_scan<<<1, 256>>>();
    k_scatter<<<NHB, 256>>>(idxs);
    k_mlp<<<MAXTILES, NT, SMEM_BYTES>>>(positions, viewdirs, features, out);
}

// round 13
// speedup vs baseline: 1.6927x; 1.0508x over previous
#include <cuda_runtime.h>
#include <cuda_fp16.h>

typedef unsigned int u32;

// ---------------- problem constants ----------------
#define NS    65536
#define KEXP  8
#define DIN   74
#define WID   64
#define DOUT  32
#define TILE  128
#define NT    256
#define MAXTILES (NS / TILE + KEXP)
#define NHB   256

// packed per-expert weight image:
// [0:8192)      W0H  [64 k][128B] swizzled
// [8192:10240)  W0HT [16 k][128B]
// [10240:10880) biases fp32: B0[64] B1[64] B2[32]
// [10880:19072) W1H  [64 k][128B]
// [19072:27264) W2H  [64 k][128B] (32 n -> 64B used)
#define WPACK_BYTES 27264
#define WP_PHASE1   10880          // W0 + biases
#define WP_PHASE2   16384          // W1 + W2

// ---------------- smem layout (bytes) ----------------
#define SM_XH0  0                  // X/H/G hi: [128 rows][128B] (k 0..63)
#define SM_XL0  16384
#define SM_XH1  32768              // X hi tail: [128 rows][48B] (k 64..79); phase2 overwrites
#define SM_XL1  38912
#define SM_W0H  45056              // phase1 image [W0H|W0HT|biases]
#define SM_W0HT 53248
#define SM_B0   55296
#define SM_B1   55552
#define SM_B2   55808
#define SM_SIDS 55936
#define SMEM_BYTES 56448           // -> 4 CTAs/SM, single wave (592 >= 520)
// phase2 overlay (XH1/XL1/W0 dead after layer 0)
#define SM_W1H  32768
#define SM_W2H  40960

#define SWZ(off) ((off) ^ (((off) >> 3) & 0x70))

// ---------------- device scratch ----------------
__device__ int g_bhist[KEXP * NHB];
__device__ int g_bbase[KEXP * NHB];
__device__ int g_offs[KEXP + 1];
__device__ int g_order[NS];
__device__ __align__(16) char g_wpack[KEXP][WPACK_BYTES];

// ---------------- helpers ----------------
__device__ __forceinline__ u32 smem_u32(const void* p) {
    u32 a; asm("{ .reg .u64 t; cvta.to.shared.u64 t, %1; cvt.u32.u64 %0, t; }" : "=r"(a) : "l"(p));
    return a;
}
__device__ __forceinline__ void ldmA(u32 a[4], u32 addr) {
    asm volatile("ldmatrix.sync.aligned.m8n8.x4.shared.b16 {%0,%1,%2,%3}, [%4];"
                 : "=r"(a[0]), "=r"(a[1]), "=r"(a[2]), "=r"(a[3]) : "r"(addr));
}
__device__ __forceinline__ void ldmBT4(u32 b[4], u32 addr) {
    asm volatile("ldmatrix.sync.aligned.m8n8.x4.trans.shared.b16 {%0,%1,%2,%3}, [%4];"
                 : "=r"(b[0]), "=r"(b[1]), "=r"(b[2]), "=r"(b[3]) : "r"(addr));
}
__device__ __forceinline__ void mma16816(float c[4], const u32 a[4], const u32 b[2]) {
    asm volatile(
        "mma.sync.aligned.m16n8k16.row.col.f32.f16.f16.f32 "
        "{%0,%1,%2,%3}, {%4,%5,%6,%7}, {%8,%9}, {%0,%1,%2,%3};"
        : "+f"(c[0]), "+f"(c[1]), "+f"(c[2]), "+f"(c[3])
        : "r"(a[0]), "r"(a[1]), "r"(a[2]), "r"(a[3]), "r"(b[0]), "r"(b[1]));
}
__device__ __forceinline__ u32 hpack(__half a, __half b) {
    __half2 t(a, b);
    return *reinterpret_cast<u32*>(&t);
}
__device__ __forceinline__ void store_split(char* sm, u32 offH, u32 offL, float v0, float v1) {
    __half h0 = __float2half_rn(v0), h1 = __float2half_rn(v1);
    float l0 = v0 - __half2float(h0), l1 = v1 - __half2float(h1);
    *(u32*)(sm + offH) = hpack(h0, h1);
    *(u32*)(sm + offL) = hpack(__float2half_rn(l0), __float2half_rn(l1));
}
__device__ __forceinline__ void split4h(float4 v, u32& h01, u32& h23) {
    h01 = hpack(__float2half_rn(v.x), __float2half_rn(v.y));
    h23 = hpack(__float2half_rn(v.z), __float2half_rn(v.w));
}
__device__ __forceinline__ void cp16(u32 dst_smem, const void* src) {
    asm volatile("cp.async.ca.shared.global [%0], [%1], 16;" :: "r"(dst_smem), "l"(src) : "memory");
}

// ---------------- merged hist + weight pre-pack ----------------
__global__ void k_pre(const int* __restrict__ idxs,
                      const float* __restrict__ W0g, const float* __restrict__ b0g,
                      const float* __restrict__ W1g, const float* __restrict__ b1g,
                      const float* __restrict__ W2g, const float* __restrict__ b2g) {
    if (blockIdx.x < NHB) {
        __shared__ int sh[KEXP];
        if (threadIdx.x < KEXP) sh[threadIdx.x] = 0;
        __syncthreads();
        atomicAdd(&sh[idxs[blockIdx.x * 256 + threadIdx.x]], 1);
        __syncthreads();
        if (threadIdx.x < KEXP) g_bhist[threadIdx.x * NHB + blockIdx.x] = sh[threadIdx.x];
        return;
    }
    int pb = blockIdx.x - NHB;
    int e = pb >> 3;
    int vt = (pb & 7) * 256 + threadIdx.x;
    char* dst = g_wpack[e];

    const float4* W0e = (const float4*)(W0g + e * DIN * WID);
    for (int i = vt; i < 80 * 16; i += 2048) {
        int k = i >> 4, cq = i & 15;
        float4 v = (k < DIN) ? W0e[k * 16 + cq] : make_float4(0.f, 0.f, 0.f, 0.f);
        u32 h01, h23; split4h(v, h01, h23);
        u32 base = 0;
        if (k >= 64) { base = 8192; k -= 64; }
        u32 off = base + SWZ((u32)(k * 128 + cq * 8));
        *(u32*)(dst + off) = h01; *(u32*)(dst + off + 4) = h23;
    }
    const float4* W1e = (const float4*)(W1g + e * WID * WID);
    for (int i = vt; i < 64 * 16; i += 2048) {
        int k = i >> 4, cq = i & 15;
        float4 v = W1e[k * 16 + cq];
        u32 h01, h23; split4h(v, h01, h23);
        u32 off = 10880 + SWZ((u32)(k * 128 + cq * 8));
        *(u32*)(dst + off) = h01; *(u32*)(dst + off + 4) = h23;
    }
    const float4* W2e = (const float4*)(W2g + e * WID * DOUT);
    for (int i = vt; i < 64 * 8; i += 2048) {
        int k = i >> 3, cq = i & 7;
        float4 v = W2e[k * 8 + cq];
        u32 h01, h23; split4h(v, h01, h23);
        u32 off = 19072 + SWZ((u32)(k * 128 + cq * 8));
        *(u32*)(dst + off) = h01; *(u32*)(dst + off + 4) = h23;
    }
    float* bd = (float*)(dst + 10240);
    for (int i = vt; i < 160; i += 2048)
        bd[i] = (i < 64) ? b0g[e * WID + i]
              : (i < 128) ? b1g[e * WID + i - 64]
              : b2g[e * DOUT + i - 128];
}

// ---------------- scan ----------------
__global__ void k_scan() {
    __shared__ int tot[KEXP];
    __shared__ int offs[KEXP];
    int w = threadIdx.x >> 5, lane = threadIdx.x & 31;
    int carry = 0;
    int excl[8];
#pragma unroll
    for (int c = 0; c < 8; c++) {
        int v = g_bhist[w * NHB + c * 32 + lane];
        int s = v;
#pragma unroll
        for (int d = 1; d < 32; d <<= 1) {
            int t = __shfl_up_sync(0xFFFFFFFFu, s, d);
            if (lane >= d) s += t;
        }
        excl[c] = carry + s - v;
        carry += __shfl_sync(0xFFFFFFFFu, s, 31);
    }
    if (lane == 0) tot[w] = carry;
    __syncthreads();
    if (threadIdx.x == 0) {
        int a = 0;
        for (int e = 0; e < KEXP; e++) { offs[e] = a; g_offs[e] = a; a += tot[e]; }
        g_offs[KEXP] = a;
    }
    __syncthreads();
    int o = offs[w];
#pragma unroll
    for (int c = 0; c < 8; c++) g_bbase[w * NHB + c * 32 + lane] = o + excl[c];
}

// ---------------- scatter ----------------
__global__ void k_scatter(const int* __restrict__ idxs) {
    __shared__ int s_loc[KEXP];
    __shared__ int s_base[KEXP];
    if (threadIdx.x < KEXP) {
        s_loc[threadIdx.x] = 0;
        s_base[threadIdx.x] = g_bbase[threadIdx.x * NHB + blockIdx.x];
    }
    __syncthreads();
    int i = blockIdx.x * 256 + threadIdx.x;
    int e = idxs[i];
    int r = atomicAdd(&s_loc[e], 1);
    g_order[s_base[e] + r] = i;
}

// ---------------- fused MMA MLP kernel (4 CTAs/SM, single wave) ----------------
__global__ void __launch_bounds__(NT, 4) k_mlp(
    const float* __restrict__ positions, const float* __restrict__ viewdirs,
    const float* __restrict__ features,
    float* __restrict__ out) {
    extern __shared__ char sm[];
    const u32 smb = smem_u32(sm);
    const int tid = threadIdx.x, lane = tid & 31, wid = tid >> 5;

    // blockIdx -> (expert, local tile)
    int e = -1, lt = 0;
    {
        int b = blockIdx.x, acc = 0;
#pragma unroll
        for (int i = 0; i < KEXP; i++) {
            int tiles = (g_offs[i + 1] - g_offs[i] + TILE - 1) / TILE;
            if (e < 0 && b < acc + tiles) { e = i; lt = b - acc; }
            acc += tiles;
        }
    }
    if (e < 0) return;
    const int base = g_offs[e] + lt * TILE;
    const int cnt = min(TILE, g_offs[e + 1] - base);

    int* sids = (int*)(sm + SM_SIDS);
    float* B0s = (float*)(sm + SM_B0);
    float* B1s = (float*)(sm + SM_B1);
    float* B2s = (float*)(sm + SM_B2);

    // ================= STAGING =================
    if (tid < TILE) {
        int n = g_order[base + min(tid, cnt - 1)];
        sids[tid] = n;
        const u32 rb = (u32)(tid * 128);
        // features: k 0..31 (store as computed, no big buffer)
        const float4* f4 = (const float4*)(features + (size_t)n * 32);
#pragma unroll
        for (int i = 0; i < 8; i++) {
            float4 f = f4[i];
            u32 o0 = SWZ(rb + (u32)(8 * i));
            u32 o1 = SWZ(rb + (u32)(8 * i + 4));
            store_split(sm, SM_XH0 + o0, SM_XL0 + o0, f.x, f.y);
            store_split(sm, SM_XH0 + o1, SM_XL0 + o1, f.z, f.w);
        }
        // k 32..47: positions + posenc(2) + q0
        {
            float p0 = positions[n * 3], p1 = positions[n * 3 + 1], p2 = positions[n * 3 + 2];
            float q0 = viewdirs[n * 3];
            float loc[16];
            loc[0] = p0; loc[1] = p1; loc[2] = p2;
#pragma unroll
            for (int s = 0; s < 2; s++) {
                float sc = (float)(1 << s);
                loc[3 + 3 * s] = __sinf(p0 * sc); loc[4 + 3 * s] = __sinf(p1 * sc); loc[5 + 3 * s] = __sinf(p2 * sc);
                loc[9 + 3 * s] = __cosf(p0 * sc); loc[10 + 3 * s] = __cosf(p1 * sc); loc[11 + 3 * s] = __cosf(p2 * sc);
            }
            loc[15] = q0;
#pragma unroll
            for (int j = 0; j < 8; j++) {
                u32 o = SWZ(rb + (u32)((32 + 2 * j) * 2));
                store_split(sm, SM_XH0 + o, SM_XL0 + o, loc[2 * j], loc[2 * j + 1]);
            }
        }
        // k 48..79: q1,q2 + viewenc(4) + zero pad
        {
            float q0 = viewdirs[n * 3], q1 = viewdirs[n * 3 + 1], q2 = viewdirs[n * 3 + 2];
            float loc[32];
            loc[0] = q1; loc[1] = q2;
#pragma unroll
            for (int s = 0; s < 4; s++) {
                float sc = (float)(1 << s);
                loc[2 + 3 * s] = __sinf(q0 * sc); loc[3 + 3 * s] = __sinf(q1 * sc); loc[4 + 3 * s] = __sinf(q2 * sc);
                loc[14 + 3 * s] = __cosf(q0 * sc); loc[15 + 3 * s] = __cosf(q1 * sc); loc[16 + 3 * s] = __cosf(q2 * sc);
            }
#pragma unroll
            for (int j = 26; j < 32; j++) loc[j] = 0.0f;
#pragma unroll
            for (int j = 0; j < 16; j++) {
                int k0 = 48 + 2 * j;
                if (k0 < 64) {
                    u32 o = SWZ(rb + (u32)(k0 * 2));
                    store_split(sm, SM_XH0 + o, SM_XL0 + o, loc[2 * j], loc[2 * j + 1]);
                } else {
                    u32 o = (u32)(tid * 48 + (k0 - 64) * 2);
                    store_split(sm, SM_XH1 + o, SM_XL1 + o, loc[2 * j], loc[2 * j + 1]);
                }
            }
        }
    } else {
        // phase-1 weight copy: W0 + biases (10880 B)
        int t2 = tid - TILE;
        const char* src = g_wpack[e];
        for (int i = t2 * 16; i < WP_PHASE1; i += 128 * 16)
            cp16(smb + SM_W0H + i, src + i);
        asm volatile("cp.async.commit_group;" ::: "memory");
        asm volatile("cp.async.wait_group 0;" ::: "memory");
    }
    __syncthreads();

    // fragment lane coordinates (warp grid: 4 M-groups x 2 N-groups)
    const int wm = wid >> 1, wn = wid & 1;
    const int amat = lane >> 3, amr = lane & 7;
    const int arow_off = ((amat & 1) << 3) + amr;
    const int akoff = amat >> 1;
    const int bk = ((lane >> 3) & 1) * 8 + (lane & 7);
    const int bnh = (lane >> 4) * 8;
    const u32 bswz = ((u32)(bk & 7)) << 4;
    const u32 brow = (u32)(bk * 128);
    const u32 bcol0 = ((u32)((wn * 32 + bnh) * 2)) ^ bswz;
    const u32 bcol1 = ((u32)((wn * 32 + 16 + bnh) * 2)) ^ bswz;

    float C[2][4][4];

    // ================= LAYER 0 (K=80, N=64) — per-kt streaming =================
#pragma unroll
    for (int mt = 0; mt < 2; mt++)
#pragma unroll
        for (int nt = 0; nt < 4; nt++)
#pragma unroll
            for (int q = 0; q < 4; q++) C[mt][nt][q] = 0.0f;

#pragma unroll
    for (int mt = 0; mt < 2; mt++) {
        int arow = wm * 32 + mt * 16 + arow_off;
        u32 arb = (u32)(arow * 128);
        int ar7 = arow & 7;
#pragma unroll
        for (int kt = 0; kt < 5; kt++) {
            u32 ah[4], al[4], b0r[4], b1r[4];
            if (kt < 4) {
                u32 off = arb + (u32)(((2 * kt + akoff) ^ ar7) << 4);
                ldmA(ah, smb + SM_XH0 + off);
                ldmA(al, smb + SM_XL0 + off);
                u32 bb = smb + SM_W0H + brow + kt * 2048;
                ldmBT4(b0r, bb + bcol0);
                ldmBT4(b1r, bb + bcol1);
            } else {
                u32 off = (u32)(arow * 48 + (akoff << 4));
                ldmA(ah, smb + SM_XH1 + off);
                ldmA(al, smb + SM_XL1 + off);
                u32 bb = smb + SM_W0HT + brow;
                ldmBT4(b0r, bb + bcol0);
                ldmBT4(b1r, bb + bcol1);
            }
#pragma unroll
            for (int sub = 0; sub < 2; sub++) {
                mma16816(C[mt][sub], ah, &b0r[2 * sub]);
                mma16816(C[mt][sub], al, &b0r[2 * sub]);
                mma16816(C[mt][2 + sub], ah, &b1r[2 * sub]);
                mma16816(C[mt][2 + sub], al, &b1r[2 * sub]);
            }
        }
    }
    __syncthreads();   // all warps done reading X(+tails) and W0

    // phase-2 weight copy (W1+W2 -> overlays dead XH1/XL1/W0 region), overlapped with epilogue
    {
        const char* src = g_wpack[e] + WP_PHASE1;
#pragma unroll
        for (int i = tid * 16; i < WP_PHASE2; i += NT * 16)
            cp16(smb + SM_W1H + i, src + i);
        asm volatile("cp.async.commit_group;" ::: "memory");
    }

    // epilogue L0: bias+relu, split, write H into XH0/XL0
#pragma unroll
    for (int mt = 0; mt < 2; mt++)
#pragma unroll
        for (int nt = 0; nt < 4; nt++) {
            int row0 = wm * 32 + mt * 16 + (lane >> 2);
            int j0 = wn * 32 + nt * 8 + (lane & 3) * 2;
            float v0 = fmaxf(C[mt][nt][0] + B0s[j0], 0.0f);
            float v1 = fmaxf(C[mt][nt][1] + B0s[j0 + 1], 0.0f);
            float v2 = fmaxf(C[mt][nt][2] + B0s[j0], 0.0f);
            float v3 = fmaxf(C[mt][nt][3] + B0s[j0 + 1], 0.0f);
            u32 oa = SWZ((u32)(row0 * 128 + j0 * 2));
            u32 ob = SWZ((u32)((row0 + 8) * 128 + j0 * 2));
            store_split(sm, SM_XH0 + oa, SM_XL0 + oa, v0, v1);
            store_split(sm, SM_XH0 + ob, SM_XL0 + ob, v2, v3);
        }
    asm volatile("cp.async.wait_group 0;" ::: "memory");
    __syncthreads();

    // ================= LAYER 1 (K=64, N=64) =================
#pragma unroll
    for (int mt = 0; mt < 2; mt++)
#pragma unroll
        for (int nt = 0; nt < 4; nt++)
#pragma unroll
            for (int q = 0; q < 4; q++) C[mt][nt][q] = 0.0f;

#pragma unroll
    for (int mt = 0; mt < 2; mt++) {
        int arow = wm * 32 + mt * 16 + arow_off;
        u32 arb = (u32)(arow * 128);
        int ar7 = arow & 7;
#pragma unroll
        for (int kt = 0; kt < 4; kt++) {
            u32 ah[4], al[4], b0r[4], b1r[4];
            u32 off = arb + (u32)(((2 * kt + akoff) ^ ar7) << 4);
            ldmA(ah, smb + SM_XH0 + off);
            ldmA(al, smb + SM_XL0 + off);
            u32 bb = smb + SM_W1H + brow + kt * 2048;
            ldmBT4(b0r, bb + bcol0);
            ldmBT4(b1r, bb + bcol1);
#pragma unroll
            for (int sub = 0; sub < 2; sub++) {
                mma16816(C[mt][sub], ah, &b0r[2 * sub]);
                mma16816(C[mt][sub], al, &b0r[2 * sub]);
                mma16816(C[mt][2 + sub], ah, &b1r[2 * sub]);
                mma16816(C[mt][2 + sub], al, &b1r[2 * sub]);
            }
        }
    }
    __syncthreads();   // done reading H before G overwrites the same panels

    // epilogue L1: bias+relu, split, write G into XH0/XL0
#pragma unroll
    for (int mt = 0; mt < 2; mt++)
#pragma unroll
        for (int nt = 0; nt < 4; nt++) {
            int row0 = wm * 32 + mt * 16 + (lane >> 2);
            int j0 = wn * 32 + nt * 8 + (lane & 3) * 2;
            float v0 = fmaxf(C[mt][nt][0] + B1s[j0], 0.0f);
            float v1 = fmaxf(C[mt][nt][1] + B1s[j0 + 1], 0.0f);
            float v2 = fmaxf(C[mt][nt][2] + B1s[j0], 0.0f);
            float v3 = fmaxf(C[mt][nt][3] + B1s[j0 + 1], 0.0f);
            u32 oa = SWZ((u32)(row0 * 128 + j0 * 2));
            u32 ob = SWZ((u32)((row0 + 8) * 128 + j0 * 2));
            store_split(sm, SM_XH0 + oa, SM_XL0 + oa, v0, v1);
            store_split(sm, SM_XH0 + ob, SM_XL0 + ob, v2, v3);
        }
    __syncthreads();

    // ================= LAYER 2 (K=64, N=32) =================
    const u32 bcol2 = ((u32)((wn * 16 + bnh) * 2)) ^ bswz;
#pragma unroll
    for (int mt = 0; mt < 2; mt++)
#pragma unroll
        for (int nt = 0; nt < 2; nt++)
#pragma unroll
            for (int q = 0; q < 4; q++) C[mt][nt][q] = 0.0f;

#pragma unroll
    for (int mt = 0; mt < 2; mt++) {
        int arow = wm * 32 + mt * 16 + arow_off;
        u32 arb = (u32)(arow * 128);
        int ar7 = arow & 7;
#pragma unroll
        for (int kt = 0; kt < 4; kt++) {
            u32 ah[4], al[4], br[4];
            u32 off = arb + (u32)(((2 * kt + akoff) ^ ar7) << 4);
            ldmA(ah, smb + SM_XH0 + off);
            ldmA(al, smb + SM_XL0 + off);
            ldmBT4(br, smb + SM_W2H + brow + kt * 2048 + bcol2);
#pragma unroll
            for (int sub = 0; sub < 2; sub++) {
                mma16816(C[mt][sub], ah, &br[2 * sub]);
                mma16816(C[mt][sub], al, &br[2 * sub]);
            }
        }
    }

    // final epilogue: bias + shuffle-coalesced float4 scatter
#pragma unroll
    for (int mt = 0; mt < 2; mt++)
#pragma unroll
        for (int nt = 0; nt < 2; nt++) {
            int row0 = wm * 32 + mt * 16 + (lane >> 2);
            int q = lane & 3;
            int j0 = wn * 16 + nt * 8 + 2 * q;
            float a0 = C[mt][nt][0] + B2s[j0];
            float a1 = C[mt][nt][1] + B2s[j0 + 1];
            float b0 = C[mt][nt][2] + B2s[j0];
            float b1 = C[mt][nt][3] + B2s[j0 + 1];
            float pa0 = __shfl_xor_sync(0xFFFFFFFFu, a0, 1);
            float pa1 = __shfl_xor_sync(0xFFFFFFFFu, a1, 1);
            float pb0 = __shfl_xor_sync(0xFFFFFFFFu, b0, 1);
            float pb1 = __shfl_xor_sync(0xFFFFFFFFu, b1, 1);
            if (!(q & 1)) {
                int colb = wn * 16 + nt * 8 + 2 * q;
                if (row0 < cnt)
                    *(float4*)(out + (size_t)sids[row0] * DOUT + colb) =
                        make_float4(a0, a1, pa0, pa1);
                if (row0 + 8 < cnt)
                    *(float4*)(out + (size_t)sids[row0 + 8] * DOUT + colb) =
                        make_float4(b0, b1, pb0, pb1);
            }
        }
}

// ---------------- launch ----------------
extern "C" void kernel_launch(void* const* d_in, const int* in_sizes, int n_in,
                              void* d_out, int out_size) {
    (void)in_sizes; (void)n_in; (void)out_size;
    const int*   idxs      = (const int*)d_in[0];
    const float* positions = (const float*)d_in[1];
    const float* viewdirs  = (const float*)d_in[2];
    const float* features  = (const float*)d_in[3];
    const float* W0 = (const float*)d_in[4];
    const float* b0 = (const float*)d_in[5];
    const float* W1 = (const float*)d_in[6];
    const float* b1 = (const float*)d_in[7];
    const float* W2 = (const float*)d_in[8];
    const float* b2 = (const float*)d_in[9];
    float* out = (float*)d_out;

    cudaFuncSetAttribute(k_mlp, cudaFuncAttributeMaxDynamicSharedMemorySize, SMEM_BYTES);

    k_pre<<<NHB + 64, 256>>>(idxs, W0, b0, W1, b1, W2, b2);
    k_scan<<<1, 256>>>();
    k_scatter<<<NHB, 256>>>(idxs);
    k_mlp<<<MAXTILES, NT, SMEM_BYTES>>>(positions, viewdirs, features, out);
}